// round 1
// baseline (speedup 1.0000x reference)
#include <cuda_runtime.h>
#include <math.h>

#define H_ 8
#define D_ 64
#define N_ 2
#define Q_ 128
#define P_ 128
#define B_ 4
#define ROWS_ 1024          // N_*Q_*B_ == N_*P_*B_
#define EPSF 1e-5f
#define TEMPF 30.0f

// ---------------- scratch (device globals; no allocation) ----------------
__device__ float  g_wk_r[H_][ROWS_][D_];   // normalized key proj (real)
__device__ float  g_wk_i[H_][ROWS_][D_];
__device__ float  g_wq_r[H_][ROWS_][D_];   // normalized query proj (pre-affine)
__device__ float  g_wq_i[H_][ROWS_][D_];
__device__ float4 g_T [ROWS_][32][16];     // per (n,q,b): 32 t-vectors (h*4+{t1..t4}) of 64 floats
__device__ float  g_S4[ROWS_][H_][4];      // bias scalars s1..s4
__device__ float  g_S [H_][N_][Q_][B_][P_];// scores -> aff

// ---------------- kernel 1: complex projections (key & query) ----------------
// grid (64 row-tiles, H, 2{key,query}), block 256
__global__ __launch_bounds__(256) void k_proj(
    const float* __restrict__ kr, const float* __restrict__ ki,
    const float* __restrict__ qr, const float* __restrict__ qi,
    const float* __restrict__ WKr, const float* __restrict__ WKrb,
    const float* __restrict__ WKi, const float* __restrict__ WKib,
    const float* __restrict__ WQr, const float* __restrict__ WQrb,
    const float* __restrict__ WQi, const float* __restrict__ WQib)
{
    int h   = blockIdx.y;
    int isQ = blockIdx.z;
    const float* xr = isQ ? qr : kr;
    const float* xi = isQ ? qi : ki;
    const float* Wr = (isQ ? WQr : WKr) + h * D_ * D_;
    const float* Wi = (isQ ? WQi : WKi) + h * D_ * D_;
    const float* br = (isQ ? WQrb : WKrb) + h * D_;
    const float* bi = (isQ ? WQib : WKib) + h * D_;
    float* outR = isQ ? &g_wq_r[h][0][0] : &g_wk_r[h][0][0];
    float* outI = isQ ? &g_wq_i[h][0][0] : &g_wk_i[h][0][0];

    __shared__ float Wr_t[D_ * D_];   // [e][d]
    __shared__ float Wi_t[D_ * D_];
    __shared__ float Xr[16][D_], Xi[16][D_];

    int t = threadIdx.x;
    for (int i = t; i < D_ * D_; i += 256) {
        int e = i / D_, d = i % D_;
        Wr_t[i] = Wr[d * D_ + e];
        Wi_t[i] = Wi[d * D_ + e];
    }
    int row0 = blockIdx.x * 16;
    for (int i = t; i < 16 * D_; i += 256) {
        int r = i / D_, d = i % D_;
        Xr[r][d] = xr[(row0 + r) * D_ + d];
        Xi[r][d] = xi[(row0 + r) * D_ + d];
    }
    __syncthreads();

    int d  = t % D_;
    int r0 = t / D_;                 // 0..3
    float bR = br[d], bI = bi[d];
    for (int r = r0; r < 16; r += 4) {
        float ar = 0.f, ai = 0.f;
#pragma unroll
        for (int e = 0; e < D_; e++) {
            float vr = Xr[r][e], vi = Xi[r][e];
            float wr = Wr_t[e * D_ + d], wi = Wi_t[e * D_ + d];
            ar += vr * wr - vi * wi;     // x_r*Wr - x_i*Wi
            ai += vr * wi + vi * wr;     // x_r*Wi + x_i*Wr
        }
        ar += bR - bI;                   // (b_r - b_i)
        ai += bR + bI;                   // (b_i + b_r)
        outR[(row0 + r) * D_ + d] = ar;
        outI[(row0 + r) * D_ + d] = ai;
    }
}

// ---------------- kernel 2: instance-norm over (p,b)/(q,b) per (h,n,d) ----------------
// grid (N_, H_, 4 arrays), block 256
__global__ __launch_bounds__(256) void k_norm()
{
    int n = blockIdx.x, h = blockIdx.y, a = blockIdx.z;
    float* base;
    if      (a == 0) base = &g_wk_r[0][0][0];
    else if (a == 1) base = &g_wk_i[0][0][0];
    else if (a == 2) base = &g_wq_r[0][0][0];
    else             base = &g_wq_i[0][0][0];
    float* x = base + ((size_t)h * ROWS_ + (size_t)n * 512) * D_;

    int t = threadIdx.x;
    int d = t % 64, c = t / 64;       // 4 chunks of 128 rows
    float s = 0.f, s2 = 0.f;
    for (int r = c * 128; r < (c + 1) * 128; r++) {
        float v = x[r * 64 + d];
        s += v; s2 += v * v;
    }
    __shared__ float Ss[4][64], S2s[4][64];
    __shared__ float mean_s[64], rstd_s[64];
    Ss[c][d] = s; S2s[c][d] = s2;
    __syncthreads();
    if (t < 64) {
        float sum  = Ss[0][t] + Ss[1][t] + Ss[2][t] + Ss[3][t];
        float sum2 = S2s[0][t] + S2s[1][t] + S2s[2][t] + S2s[3][t];
        float m   = sum * (1.f / 512.f);
        float var = sum2 * (1.f / 512.f) - m * m;
        mean_s[t] = m;
        rstd_s[t] = rsqrtf(var + EPSF);
    }
    __syncthreads();
    for (int i = t; i < 512 * 64; i += 256) {
        int dd = i % 64;
        x[i] = (x[i] - mean_s[dd]) * rstd_s[dd];
    }
}

// ---------------- kernel 3: t-vectors + bias scalars ----------------
// grid (64 point-groups of 16, H), block 256
__global__ __launch_bounds__(256) void k_tvec(
    const float* __restrict__ WKRr, const float* __restrict__ WKRrb,
    const float* __restrict__ WKRi, const float* __restrict__ WKRib,
    const float* __restrict__ wr_r_g, const float* __restrict__ wr_r_bt,
    const float* __restrict__ wr_i_g, const float* __restrict__ wr_i_bt)
{
    int g = blockIdx.x, h = blockIdx.y;
    __shared__ float Wr_s[D_ * D_];  // natural [d][e]
    __shared__ float Wi_s[D_ * D_];
    __shared__ float ur[16][D_], ui[16][D_];
    int t = threadIdx.x;
    const float* Wr = WKRr + h * D_ * D_;
    const float* Wi = WKRi + h * D_ * D_;
    for (int i = t; i < D_ * D_; i += 256) { Wr_s[i] = Wr[i]; Wi_s[i] = Wi[i]; }
    int pt0 = g * 16;
    for (int i = t; i < 16 * D_; i += 256) {
        int l = i / D_, d = i % D_;
        float yr = g_wq_r[h][pt0 + l][d];
        float yi = g_wq_i[h][pt0 + l][d];
        ur[l][d] = yr * wr_r_g[h * D_ + d] + wr_r_bt[h * D_ + d];  // wr_qr
        ui[l][d] = yi * wr_i_g[h * D_ + d] + wr_i_bt[h * D_ + d];  // wr_qi
    }
    __syncthreads();
    // t1=Wr^T u_r, t2=Wi^T u_r, t3=Wr^T u_i, t4=Wi^T u_i
    for (int idx = t; idx < 16 * 4 * 64; idx += 256) {
        int e   = idx % 64;
        int vec = (idx / 64) % 4;
        int l   = idx / 256;
        const float* W = (vec & 1) ? Wi_s : Wr_s;
        const float* u = (vec >= 2) ? ui[l] : ur[l];
        float acc = 0.f;
#pragma unroll
        for (int dd = 0; dd < 64; dd++) acc += W[dd * 64 + e] * u[dd];
        ((float*)&g_T[pt0 + l][h * 4 + vec][0])[e] = acc;
    }
    if (t < 64) {
        int l = t / 4, si = t % 4;
        const float* br = WKRrb + h * D_;
        const float* bi = WKRib + h * D_;
        float acc = 0.f;
        for (int dd = 0; dd < 64; dd++) {
            float bm = br[dd] - bi[dd];
            float bp = br[dd] + bi[dd];
            float v;
            if      (si == 0) v = bm * ur[l][dd];   // s1
            else if (si == 1) v = bp * ui[l][dd];   // s2
            else if (si == 2) v = bm * ui[l][dd];   // s3
            else              v = bp * ur[l][dd];   // s4
            acc += v;
        }
        g_S4[pt0 + l][h][si] = acc;
    }
}

// ---------------- kernel 4: AC magnitudes ----------------
// grid (8 q-tiles of 16, B_, H_*N_), block 256
__global__ __launch_bounds__(256) void k_ac(
    const float* __restrict__ ww_r_g, const float* __restrict__ ww_r_bt,
    const float* __restrict__ ww_i_g, const float* __restrict__ ww_i_bt)
{
    int qt = blockIdx.x;
    int b  = blockIdx.y;
    int h  = blockIdx.z / N_, n = blockIdx.z % N_;
    __shared__ float wwr[16][D_], wwi[16][D_];
    __shared__ float wkr[32][65], wki[32][65];
    int t = threadIdx.x;
    for (int i = t; i < 16 * D_; i += 256) {
        int ql = i / D_, d = i % D_;
        int q  = qt * 16 + ql;
        int row = (n * Q_ + q) * B_ + b;
        float yr = g_wq_r[h][row][d];
        float yi = g_wq_i[h][row][d];
        wwr[ql][d] = yr * ww_r_g[h * D_ + d] + ww_r_bt[h * D_ + d];
        wwi[ql][d] = yi * ww_i_g[h * D_ + d] + ww_i_bt[h * D_ + d];
    }
    for (int c = 0; c < 4; c++) {
        __syncthreads();
        for (int i = t; i < 32 * D_; i += 256) {
            int pl = i / D_, d = i % D_;
            int p  = c * 32 + pl;
            int row = (n * P_ + p) * B_ + b;
            wkr[pl][d] = g_wk_r[h][row][d];
            wki[pl][d] = g_wk_i[h][row][d];
        }
        __syncthreads();
        for (int idx = t; idx < 512; idx += 256) {
            int ql = idx / 32, pl = idx % 32;
            float accR = 0.f, accI = 0.f;
#pragma unroll
            for (int d = 0; d < 64; d++) {
                float kr = wkr[pl][d], ki = wki[pl][d];
                float qr = wwr[ql][d], qi = wwi[ql][d];
                accR += kr * qr - ki * qi;
                accI += kr * qi + ki * qr;
            }
            g_S[h][n][qt * 16 + ql][b][c * 32 + pl] = sqrtf(accR * accR + accI * accI);
        }
    }
}

// ---------------- kernel 5: BD (the hot loop) ----------------
// grid 1024 points (n,q,b), block 128 (thread = p)
__global__ __launch_bounds__(128) void k_bd(
    const float* __restrict__ emb_r, const float* __restrict__ emb_i)
{
    int pt = blockIdx.x;
    int b  = pt % B_;
    int q  = (pt / B_) % Q_;
    int n  = pt / (B_ * Q_);

    __shared__ float4 T_s[32][16];
    __shared__ float  s_s[H_][4];
    int t = threadIdx.x;
    const float4* Tg = &g_T[pt][0][0];
    for (int i = t; i < 32 * 16; i += 128) ((float4*)T_s)[i] = Tg[i];
    for (int i = t; i < H_ * 4; i += 128) ((float*)s_s)[i] = ((const float*)&g_S4[pt][0][0])[i];
    __syncthreads();

    int p = t;
    const float4* rRR = (const float4*)(emb_r + ((((size_t)n * Q_ + q) * P_ + p) * B_ + b) * D_);
    const float4* rIR = (const float4*)(emb_i + ((((size_t)n * Q_ + q) * P_ + p) * B_ + b) * D_);
    const float4* rRC = (const float4*)(emb_r + ((((size_t)n * Q_ + p) * P_ + q) * B_ + b) * D_);
    const float4* rIC = (const float4*)(emb_i + ((((size_t)n * Q_ + p) * P_ + q) * B_ + b) * D_);

    float bdr[H_], bdi[H_];
#pragma unroll
    for (int h = 0; h < H_; h++) { bdr[h] = 0.f; bdi[h] = 0.f; }

#pragma unroll 2
    for (int d4 = 0; d4 < 16; d4++) {
        float4 er = __ldg(rRR + d4);
        float4 ei = __ldg(rIR + d4);
        float4 fr = __ldg(rRC + d4);
        float4 fi = __ldg(rIC + d4);
#pragma unroll
        for (int h = 0; h < H_; h++) {
            float4 t1 = T_s[4 * h + 0][d4];
            float4 t2 = T_s[4 * h + 1][d4];
            float4 t3 = T_s[4 * h + 2][d4];
            float4 t4 = T_s[4 * h + 3][d4];
            bdr[h] += er.x * t1.x - ei.x * t2.x - fr.x * t4.x - fi.x * t3.x;
            bdi[h] += er.x * t3.x - ei.x * t4.x + fr.x * t2.x + fi.x * t1.x;
            bdr[h] += er.y * t1.y - ei.y * t2.y - fr.y * t4.y - fi.y * t3.y;
            bdi[h] += er.y * t3.y - ei.y * t4.y + fr.y * t2.y + fi.y * t1.y;
            bdr[h] += er.z * t1.z - ei.z * t2.z - fr.z * t4.z - fi.z * t3.z;
            bdi[h] += er.z * t3.z - ei.z * t4.z + fr.z * t2.z + fi.z * t1.z;
            bdr[h] += er.w * t1.w - ei.w * t2.w - fr.w * t4.w - fi.w * t3.w;
            bdi[h] += er.w * t3.w - ei.w * t4.w + fr.w * t2.w + fi.w * t1.w;
        }
    }

#pragma unroll
    for (int h = 0; h < H_; h++) {
        float r  = bdr[h] + s_s[h][0] - s_s[h][1];
        float im = bdi[h] + s_s[h][2] + s_s[h][3];
        float mag = sqrtf(r * r + im * im);
        float* Sp = &g_S[h][n][q][b][p];
        *Sp = *Sp + mag;
    }
}

// ---------------- kernel 6: softmax over b (axis -1, size 4) ----------------
// grid 1024, block 256: one thread per (h,n,q,p)
__global__ __launch_bounds__(256) void k_softmax()
{
    int idx = blockIdx.x * 256 + threadIdx.x;   // 0..262143
    int p  = idx % P_;
    int q  = (idx / P_) % Q_;
    int hn = idx / (P_ * Q_);                   // h*N_+n
    float* base = &g_S[0][0][0][0][0] + (((size_t)hn * Q_ + q) * B_) * P_ + p;
    float v0 = base[0 * P_] * TEMPF;
    float v1 = base[1 * P_] * TEMPF;
    float v2 = base[2 * P_] * TEMPF;
    float v3 = base[3 * P_] * TEMPF;
    float m = fmaxf(fmaxf(v0, v1), fmaxf(v2, v3));
    v0 = __expf(v0 - m); v1 = __expf(v1 - m); v2 = __expf(v2 - m); v3 = __expf(v3 - m);
    float inv = 1.f / (v0 + v1 + v2 + v3);
    base[0 * P_] = v0 * inv;
    base[1 * P_] = v1 * inv;
    base[2 * P_] = v2 * inv;
    base[3 * P_] = v3 * inv;
}

// ---------------- kernel 7: output aggregation over p ----------------
// grid 1024 points (n,q,b), block 512 (thread = (h,d))
__global__ __launch_bounds__(512) void k_out(
    const float* __restrict__ vr, const float* __restrict__ vi,
    float* __restrict__ out)
{
    int pt = blockIdx.x;
    int b  = pt % B_;
    int q  = (pt / B_) % Q_;
    int n  = pt / (B_ * Q_);

    __shared__ float aff[H_][P_];
    __shared__ float vsr[16][D_], vsi[16][D_];
    int t = threadIdx.x;
    for (int i = t; i < H_ * P_; i += 512) {
        int h = i / P_, p = i % P_;
        aff[h][p] = g_S[h][n][q][b][p];
    }
    int h = t / D_, d = t % D_;
    float ar = 0.f, ai = 0.f;
    for (int c = 0; c < 8; c++) {
        __syncthreads();
        for (int i = t; i < 16 * D_; i += 512) {
            int pl = i / D_, dd = i % D_;
            int p  = c * 16 + pl;
            size_t off = (((size_t)n * P_ + p) * B_ + b) * D_ + dd;
            vsr[pl][dd] = vr[off];
            vsi[pl][dd] = vi[off];
        }
        __syncthreads();
#pragma unroll
        for (int pl = 0; pl < 16; pl++) {
            float a = aff[h][c * 16 + pl];
            ar += a * vsr[pl][d];
            ai += a * vsi[pl][d];
        }
    }
    size_t o = (((size_t)n * Q_ + q) * B_ + b) * (H_ * D_) + h * D_ + d;
    out[o] = ar;
    out[o + (size_t)N_ * Q_ * B_ * H_ * D_] = ai;
}

// ---------------- launch ----------------
extern "C" void kernel_launch(void* const* d_in, const int* in_sizes, int n_in,
                              void* d_out, int out_size)
{
    const float* query_r = (const float*)d_in[0];
    const float* query_i = (const float*)d_in[1];
    const float* key_r   = (const float*)d_in[2];
    const float* key_i   = (const float*)d_in[3];
    const float* val_r   = (const float*)d_in[4];
    const float* val_i   = (const float*)d_in[5];
    const float* emb_r   = (const float*)d_in[6];
    const float* emb_i   = (const float*)d_in[7];
    const float* WKr_w   = (const float*)d_in[8];
    const float* WKr_b   = (const float*)d_in[9];
    const float* WKi_w   = (const float*)d_in[10];
    const float* WKi_b   = (const float*)d_in[11];
    const float* WKRr_w  = (const float*)d_in[12];
    const float* WKRr_b  = (const float*)d_in[13];
    const float* WKRi_w  = (const float*)d_in[14];
    const float* WKRi_b  = (const float*)d_in[15];
    const float* WQr_w   = (const float*)d_in[16];
    const float* WQr_b   = (const float*)d_in[17];
    const float* WQi_w   = (const float*)d_in[18];
    const float* WQi_b   = (const float*)d_in[19];
    const float* ww_r_g  = (const float*)d_in[20];
    const float* ww_r_bt = (const float*)d_in[21];
    const float* ww_i_g  = (const float*)d_in[22];
    const float* ww_i_bt = (const float*)d_in[23];
    const float* wr_r_g  = (const float*)d_in[24];
    const float* wr_r_bt = (const float*)d_in[25];
    const float* wr_i_g  = (const float*)d_in[26];
    const float* wr_i_bt = (const float*)d_in[27];

    k_proj<<<dim3(64, H_, 2), 256>>>(key_r, key_i, query_r, query_i,
                                     WKr_w, WKr_b, WKi_w, WKi_b,
                                     WQr_w, WQr_b, WQi_w, WQi_b);
    k_norm<<<dim3(N_, H_, 4), 256>>>();
    k_tvec<<<dim3(64, H_), 256>>>(WKRr_w, WKRr_b, WKRi_w, WKRi_b,
                                  wr_r_g, wr_r_bt, wr_i_g, wr_i_bt);
    k_ac<<<dim3(8, B_, H_ * N_), 256>>>(ww_r_g, ww_r_bt, ww_i_g, ww_i_bt);
    k_bd<<<ROWS_, 128>>>(emb_r, emb_i);
    k_softmax<<<1024, 256>>>();
    k_out<<<ROWS_, 512>>>(val_r, val_i, (float*)d_out);
}

// round 2
// speedup vs baseline: 1.3326x; 1.3326x over previous
#include <cuda_runtime.h>
#include <math.h>

#define H_ 8
#define D_ 64
#define N_ 2
#define Q_ 128
#define P_ 128
#define B_ 4
#define ROWS_ 1024          // N_*Q_*B_ == N_*P_*B_
#define EPSF 1e-5f
#define TEMPF 30.0f

// ---------------- packed fp32x2 FMA (sm_103a FFMA2) ----------------
__device__ __forceinline__ void fma2(float2& d, float2 a, float2 b) {
    asm("fma.rn.f32x2 %0, %1, %2, %0;"
        : "+l"(reinterpret_cast<unsigned long long&>(d))
        : "l"(reinterpret_cast<unsigned long long&>(a)),
          "l"(reinterpret_cast<unsigned long long&>(b)));
}
__device__ __forceinline__ float2 dup2(float v) { return make_float2(v, v); }
__device__ __forceinline__ float2 neg2(float2 v) { return make_float2(-v.x, -v.y); }

// ---------------- scratch (device globals; no allocation) ----------------
__device__ float  g_wk_r[H_][ROWS_][D_];
__device__ float  g_wk_i[H_][ROWS_][D_];
__device__ float  g_wq_r[H_][ROWS_][D_];
__device__ float  g_wq_i[H_][ROWS_][D_];
__device__ float4 g_T [ROWS_][32][16];     // per (n,q,b): 32 t-vectors of 64 floats
__device__ float  g_S4[ROWS_][H_][4];      // bias scalars s1..s4
__device__ float  g_S [H_][N_][Q_][B_][P_];// scores -> aff

// ---------------- kernel 1: complex projections, register-tiled ----------------
// grid (16 row-tiles of 64, H, 2{key,query}), block 256 = 16x16, thread 4row x 4d
__global__ __launch_bounds__(256) void k_proj(
    const float* __restrict__ kr, const float* __restrict__ ki,
    const float* __restrict__ qr, const float* __restrict__ qi,
    const float* __restrict__ WKr, const float* __restrict__ WKrb,
    const float* __restrict__ WKi, const float* __restrict__ WKib,
    const float* __restrict__ WQr, const float* __restrict__ WQrb,
    const float* __restrict__ WQi, const float* __restrict__ WQib)
{
    int h   = blockIdx.y;
    int isQ = blockIdx.z;
    const float* xr = isQ ? qr : kr;
    const float* xi = isQ ? qi : ki;
    const float* Wr = (isQ ? WQr : WKr) + h * D_ * D_;
    const float* Wi = (isQ ? WQi : WKi) + h * D_ * D_;
    const float* br = (isQ ? WQrb : WKrb) + h * D_;
    const float* bi = (isQ ? WQib : WKib) + h * D_;
    float* outR = isQ ? &g_wq_r[h][0][0] : &g_wk_r[h][0][0];
    float* outI = isQ ? &g_wq_i[h][0][0] : &g_wk_i[h][0][0];

    __shared__ float Wr_t[D_][66];   // [e][d], pad 66 keeps float2 8B-aligned
    __shared__ float Wi_t[D_][66];
    __shared__ float Xr[64][D_], Xi[64][D_];

    int t = threadIdx.x;
    for (int i = t; i < D_ * D_; i += 256) {
        int d = i >> 6, e = i & 63;
        Wr_t[e][d] = Wr[i];
        Wi_t[e][d] = Wi[i];
    }
    int row0 = blockIdx.x * 64;
    const float4* xr4 = (const float4*)(xr + (size_t)row0 * D_);
    const float4* xi4 = (const float4*)(xi + (size_t)row0 * D_);
    for (int i = t; i < 64 * D_ / 4; i += 256) {
        ((float4*)Xr)[i] = xr4[i];
        ((float4*)Xi)[i] = xi4[i];
    }
    __syncthreads();

    int tx = t & 15, ty = t >> 4;
    int d0 = tx * 4, r0 = ty * 4;

    float2 ar[4][2], ai[4][2];
#pragma unroll
    for (int i = 0; i < 4; i++)
#pragma unroll
        for (int j = 0; j < 2; j++) { ar[i][j] = make_float2(0.f, 0.f); ai[i][j] = make_float2(0.f, 0.f); }

#pragma unroll 4
    for (int e = 0; e < 64; e++) {
        float2 wr0 = *(const float2*)&Wr_t[e][d0];
        float2 wr1 = *(const float2*)&Wr_t[e][d0 + 2];
        float2 wi0 = *(const float2*)&Wi_t[e][d0];
        float2 wi1 = *(const float2*)&Wi_t[e][d0 + 2];
        float2 nwi0 = neg2(wi0), nwi1 = neg2(wi1);
#pragma unroll
        for (int i = 0; i < 4; i++) {
            float2 v2r = dup2(Xr[r0 + i][e]);
            float2 v2i = dup2(Xi[r0 + i][e]);
            fma2(ar[i][0], v2r, wr0);  fma2(ar[i][0], v2i, nwi0);
            fma2(ar[i][1], v2r, wr1);  fma2(ar[i][1], v2i, nwi1);
            fma2(ai[i][0], v2r, wi0);  fma2(ai[i][0], v2i, wr0);
            fma2(ai[i][1], v2r, wi1);  fma2(ai[i][1], v2i, wr1);
        }
    }

    float2 bR0 = *(const float2*)&br[d0];
    float2 bR1 = *(const float2*)&br[d0 + 2];
    float2 bI0 = *(const float2*)&bi[d0];
    float2 bI1 = *(const float2*)&bi[d0 + 2];
#pragma unroll
    for (int i = 0; i < 4; i++) {
        ar[i][0].x += bR0.x - bI0.x;  ar[i][0].y += bR0.y - bI0.y;
        ar[i][1].x += bR1.x - bI1.x;  ar[i][1].y += bR1.y - bI1.y;
        ai[i][0].x += bR0.x + bI0.x;  ai[i][0].y += bR0.y + bI0.y;
        ai[i][1].x += bR1.x + bI1.x;  ai[i][1].y += bR1.y + bI1.y;
        float2* oR = (float2*)(outR + (size_t)(row0 + r0 + i) * D_ + d0);
        float2* oI = (float2*)(outI + (size_t)(row0 + r0 + i) * D_ + d0);
        oR[0] = ar[i][0];  oR[1] = ar[i][1];
        oI[0] = ai[i][0];  oI[1] = ai[i][1];
    }
}

// ---------------- kernel 2: instance-norm over (p,b) per (h,n,d) ----------------
__global__ __launch_bounds__(256) void k_norm()
{
    int n = blockIdx.x, h = blockIdx.y, a = blockIdx.z;
    float* base;
    if      (a == 0) base = &g_wk_r[0][0][0];
    else if (a == 1) base = &g_wk_i[0][0][0];
    else if (a == 2) base = &g_wq_r[0][0][0];
    else             base = &g_wq_i[0][0][0];
    float* x = base + ((size_t)h * ROWS_ + (size_t)n * 512) * D_;

    int t = threadIdx.x;
    int d = t % 64, c = t / 64;
    float s = 0.f, s2 = 0.f;
    for (int r = c * 128; r < (c + 1) * 128; r++) {
        float v = x[r * 64 + d];
        s += v; s2 += v * v;
    }
    __shared__ float Ss[4][64], S2s[4][64];
    __shared__ float mean_s[64], rstd_s[64];
    Ss[c][d] = s; S2s[c][d] = s2;
    __syncthreads();
    if (t < 64) {
        float sum  = Ss[0][t] + Ss[1][t] + Ss[2][t] + Ss[3][t];
        float sum2 = S2s[0][t] + S2s[1][t] + S2s[2][t] + S2s[3][t];
        float m   = sum * (1.f / 512.f);
        float var = sum2 * (1.f / 512.f) - m * m;
        mean_s[t] = m;
        rstd_s[t] = rsqrtf(var + EPSF);
    }
    __syncthreads();
    for (int i = t; i < 512 * 64; i += 256) {
        int dd = i % 64;
        x[i] = (x[i] - mean_s[dd]) * rstd_s[dd];
    }
}

// ---------------- kernel 3: t-vectors (GEMM) + bias scalars ----------------
// grid (16 row-tiles of 64, H), block 256 = 16x16, thread 4row x 4e, 4 outputs
__global__ __launch_bounds__(256) void k_tvec(
    const float* __restrict__ WKRr, const float* __restrict__ WKRrb,
    const float* __restrict__ WKRi, const float* __restrict__ WKRib,
    const float* __restrict__ wr_r_g, const float* __restrict__ wr_r_bt,
    const float* __restrict__ wr_i_g, const float* __restrict__ wr_i_bt)
{
    int h = blockIdx.y;
    int pt0 = blockIdx.x * 64;
    __shared__ float Ur[64][D_], Ui[64][D_];
    __shared__ float Wr_s[64][66], Wi_s[64][66];   // [d][e], natural layout
    __shared__ float bm_s[64], bp_s[64];

    int t = threadIdx.x;
    const float* Wr = WKRr + h * D_ * D_;
    const float* Wi = WKRi + h * D_ * D_;
    for (int i = t; i < D_ * D_; i += 256) {
        int dd = i >> 6, e = i & 63;
        Wr_s[dd][e] = Wr[i];
        Wi_s[dd][e] = Wi[i];
    }
    for (int i = t; i < 64 * D_; i += 256) {
        int l = i >> 6, d = i & 63;
        float yr = g_wq_r[h][pt0 + l][d];
        float yi = g_wq_i[h][pt0 + l][d];
        Ur[l][d] = yr * wr_r_g[h * D_ + d] + wr_r_bt[h * D_ + d];
        Ui[l][d] = yi * wr_i_g[h * D_ + d] + wr_i_bt[h * D_ + d];
    }
    if (t < 64) {
        float brv = WKRrb[h * D_ + t], biv = WKRib[h * D_ + t];
        bm_s[t] = brv - biv;
        bp_s[t] = brv + biv;
    }
    __syncthreads();

    int tx = t & 15, ty = t >> 4;
    int e0 = tx * 4, r0 = ty * 4;

    float2 t1[4][2], t2[4][2], t3[4][2], t4[4][2];
#pragma unroll
    for (int i = 0; i < 4; i++)
#pragma unroll
        for (int j = 0; j < 2; j++) {
            t1[i][j] = make_float2(0.f, 0.f); t2[i][j] = make_float2(0.f, 0.f);
            t3[i][j] = make_float2(0.f, 0.f); t4[i][j] = make_float2(0.f, 0.f);
        }

#pragma unroll 4
    for (int dd = 0; dd < 64; dd++) {
        float2 wr0 = *(const float2*)&Wr_s[dd][e0];
        float2 wr1 = *(const float2*)&Wr_s[dd][e0 + 2];
        float2 wi0 = *(const float2*)&Wi_s[dd][e0];
        float2 wi1 = *(const float2*)&Wi_s[dd][e0 + 2];
#pragma unroll
        for (int i = 0; i < 4; i++) {
            float2 u2r = dup2(Ur[r0 + i][dd]);
            float2 u2i = dup2(Ui[r0 + i][dd]);
            fma2(t1[i][0], u2r, wr0);  fma2(t1[i][1], u2r, wr1);
            fma2(t2[i][0], u2r, wi0);  fma2(t2[i][1], u2r, wi1);
            fma2(t3[i][0], u2i, wr0);  fma2(t3[i][1], u2i, wr1);
            fma2(t4[i][0], u2i, wi0);  fma2(t4[i][1], u2i, wi1);
        }
    }

#pragma unroll
    for (int i = 0; i < 4; i++) {
        float* base = (float*)&g_T[pt0 + r0 + i][h * 4][0];   // 4 vecs x 64 floats
        *(float2*)(base +   0 + e0) = t1[i][0];  *(float2*)(base +   0 + e0 + 2) = t1[i][1];
        *(float2*)(base +  64 + e0) = t2[i][0];  *(float2*)(base +  64 + e0 + 2) = t2[i][1];
        *(float2*)(base + 128 + e0) = t3[i][0];  *(float2*)(base + 128 + e0 + 2) = t3[i][1];
        *(float2*)(base + 192 + e0) = t4[i][0];  *(float2*)(base + 192 + e0 + 2) = t4[i][1];
    }

    if (tx == 0) {
#pragma unroll
        for (int i = 0; i < 4; i++) {
            float s1 = 0.f, s2v = 0.f, s3 = 0.f, s4 = 0.f;
            for (int dd = 0; dd < 64; dd++) {
                float u_r = Ur[r0 + i][dd], u_i = Ui[r0 + i][dd];
                float bm = bm_s[dd], bp = bp_s[dd];
                s1 += bm * u_r;  s2v += bp * u_i;
                s3 += bm * u_i;  s4 += bp * u_r;
            }
            int pt = pt0 + r0 + i;
            g_S4[pt][h][0] = s1;  g_S4[pt][h][1] = s2v;
            g_S4[pt][h][2] = s3;  g_S4[pt][h][3] = s4;
        }
    }
}

// ---------------- kernel 4: AC magnitudes, register-tiled complex GEMM ----------------
// grid (4 q-quarters, B, H*N), block 256: tx(32)->p lanes, ty(8)->q group of 4
__global__ __launch_bounds__(256) void k_ac(
    const float* __restrict__ ww_r_g, const float* __restrict__ ww_r_bt,
    const float* __restrict__ ww_i_g, const float* __restrict__ ww_i_bt)
{
    int b = blockIdx.y;
    int h = blockIdx.z / N_, n = blockIdx.z % N_;
    int q0 = blockIdx.x * 32;

    __shared__ float wqr[32][D_], wqi[32][D_];       // [q][d]
    __shared__ float wkrT[64][130], wkiT[64][130];   // [d][p], padded

    int t = threadIdx.x;
    for (int i = t; i < 32 * D_; i += 256) {
        int q = i >> 6, d = i & 63;
        int row = (n * Q_ + q0 + q) * B_ + b;
        float yr = g_wq_r[h][row][d];
        float yi = g_wq_i[h][row][d];
        wqr[q][d] = yr * ww_r_g[h * D_ + d] + ww_r_bt[h * D_ + d];
        wqi[q][d] = yi * ww_i_g[h * D_ + d] + ww_i_bt[h * D_ + d];
    }
    for (int i = t; i < 128 * D_; i += 256) {
        int p = i >> 6, d = i & 63;
        int row = (n * P_ + p) * B_ + b;
        wkrT[d][p] = g_wk_r[h][row][d];
        wkiT[d][p] = g_wk_i[h][row][d];
    }
    __syncthreads();

    int tx = t & 31, ty = t >> 5;
    int lq0 = ty * 4;

    float2 accR[2][4], accI[2][4];   // [q-pair][p j], p_j = tx + 32*j
#pragma unroll
    for (int ii = 0; ii < 2; ii++)
#pragma unroll
        for (int j = 0; j < 4; j++) { accR[ii][j] = make_float2(0.f, 0.f); accI[ii][j] = make_float2(0.f, 0.f); }

#pragma unroll 4
    for (int d = 0; d < 64; d++) {
        float qr_[4], qi_[4], kr_[4], ki_[4];
#pragma unroll
        for (int i = 0; i < 4; i++) { qr_[i] = wqr[lq0 + i][d]; qi_[i] = wqi[lq0 + i][d]; }
#pragma unroll
        for (int j = 0; j < 4; j++) { kr_[j] = wkrT[d][tx + 32 * j]; ki_[j] = wkiT[d][tx + 32 * j]; }
#pragma unroll
        for (int ii = 0; ii < 2; ii++) {
            float2 qr2  = make_float2(qr_[2 * ii], qr_[2 * ii + 1]);
            float2 qi2  = make_float2(qi_[2 * ii], qi_[2 * ii + 1]);
            float2 nqi2 = neg2(qi2);
#pragma unroll
            for (int j = 0; j < 4; j++) {
                float2 kr2 = dup2(kr_[j]);
                float2 ki2 = dup2(ki_[j]);
                fma2(accR[ii][j], qr2, kr2);  fma2(accR[ii][j], nqi2, ki2);
                fma2(accI[ii][j], qr2, ki2);  fma2(accI[ii][j], qi2,  kr2);
            }
        }
    }

#pragma unroll
    for (int ii = 0; ii < 2; ii++)
#pragma unroll
        for (int j = 0; j < 4; j++) {
            int qg0 = q0 + lq0 + 2 * ii;
            int p   = tx + 32 * j;
            float r0v = accR[ii][j].x, i0v = accI[ii][j].x;
            float r1v = accR[ii][j].y, i1v = accI[ii][j].y;
            g_S[h][n][qg0][b][p]     = sqrtf(r0v * r0v + i0v * i0v);
            g_S[h][n][qg0 + 1][b][p] = sqrtf(r1v * r1v + i1v * i1v);
        }
}

// ---------------- kernel 5: BD (hot loop), f32x2, 256 threads (h-split) ----------------
__global__ __launch_bounds__(256) void k_bd(
    const float* __restrict__ emb_r, const float* __restrict__ emb_i)
{
    int pt = blockIdx.x;
    int b  = pt % B_;
    int q  = (pt / B_) % Q_;
    int n  = pt / (B_ * Q_);

    __shared__ float4 T_s[32][16];
    __shared__ float  s_s[32];
    int t = threadIdx.x;
    const float4* Tg = &g_T[pt][0][0];
    for (int i = t; i < 32 * 16; i += 256) ((float4*)T_s)[i] = Tg[i];
    if (t < 32) s_s[t] = ((const float*)&g_S4[pt][0][0])[t];
    __syncthreads();

    int p  = t & 127;
    int hh = t >> 7;           // 0/1: handles h in [hh*4, hh*4+4)
    int h0 = hh * 4;

    const float4* rRR = (const float4*)(emb_r + ((((size_t)n * Q_ + q) * P_ + p) * B_ + b) * D_);
    const float4* rIR = (const float4*)(emb_i + ((((size_t)n * Q_ + q) * P_ + p) * B_ + b) * D_);
    const float4* rRC = (const float4*)(emb_r + ((((size_t)n * Q_ + p) * P_ + q) * B_ + b) * D_);
    const float4* rIC = (const float4*)(emb_i + ((((size_t)n * Q_ + p) * P_ + q) * B_ + b) * D_);

    float2 bdrP[4][2], bdrM[4][2], bdiP[4][2], bdiM[4][2];
#pragma unroll
    for (int hl = 0; hl < 4; hl++)
#pragma unroll
        for (int j = 0; j < 2; j++) {
            bdrP[hl][j] = make_float2(0.f, 0.f); bdrM[hl][j] = make_float2(0.f, 0.f);
            bdiP[hl][j] = make_float2(0.f, 0.f); bdiM[hl][j] = make_float2(0.f, 0.f);
        }

#pragma unroll 2
    for (int d4 = 0; d4 < 16; d4++) {
        float4 er = __ldg(rRR + d4);
        float4 ei = __ldg(rIR + d4);
        float4 fr = __ldg(rRC + d4);
        float4 fi = __ldg(rIC + d4);
        float2 er_a = make_float2(er.x, er.y), er_b = make_float2(er.z, er.w);
        float2 ei_a = make_float2(ei.x, ei.y), ei_b = make_float2(ei.z, ei.w);
        float2 fr_a = make_float2(fr.x, fr.y), fr_b = make_float2(fr.z, fr.w);
        float2 fi_a = make_float2(fi.x, fi.y), fi_b = make_float2(fi.z, fi.w);
#pragma unroll
        for (int hl = 0; hl < 4; hl++) {
            int hv = h0 + hl;
            float4 T1 = T_s[4 * hv + 0][d4];
            float4 T2 = T_s[4 * hv + 1][d4];
            float4 T3 = T_s[4 * hv + 2][d4];
            float4 T4 = T_s[4 * hv + 3][d4];
            float2 T1a = make_float2(T1.x, T1.y), T1b = make_float2(T1.z, T1.w);
            float2 T2a = make_float2(T2.x, T2.y), T2b = make_float2(T2.z, T2.w);
            float2 T3a = make_float2(T3.x, T3.y), T3b = make_float2(T3.z, T3.w);
            float2 T4a = make_float2(T4.x, T4.y), T4b = make_float2(T4.z, T4.w);
            fma2(bdrP[hl][0], er_a, T1a);  fma2(bdrP[hl][1], er_b, T1b);
            fma2(bdrM[hl][0], ei_a, T2a);  fma2(bdrM[hl][1], ei_b, T2b);
            fma2(bdrM[hl][0], fr_a, T4a);  fma2(bdrM[hl][1], fr_b, T4b);
            fma2(bdrM[hl][0], fi_a, T3a);  fma2(bdrM[hl][1], fi_b, T3b);
            fma2(bdiP[hl][0], er_a, T3a);  fma2(bdiP[hl][1], er_b, T3b);
            fma2(bdiP[hl][0], fr_a, T2a);  fma2(bdiP[hl][1], fr_b, T2b);
            fma2(bdiP[hl][0], fi_a, T1a);  fma2(bdiP[hl][1], fi_b, T1b);
            fma2(bdiM[hl][0], ei_a, T4a);  fma2(bdiM[hl][1], ei_b, T4b);
        }
    }

#pragma unroll
    for (int hl = 0; hl < 4; hl++) {
        int hv = h0 + hl;
        float rp = (bdrP[hl][0].x + bdrP[hl][0].y) + (bdrP[hl][1].x + bdrP[hl][1].y);
        float rm = (bdrM[hl][0].x + bdrM[hl][0].y) + (bdrM[hl][1].x + bdrM[hl][1].y);
        float ip = (bdiP[hl][0].x + bdiP[hl][0].y) + (bdiP[hl][1].x + bdiP[hl][1].y);
        float im = (bdiM[hl][0].x + bdiM[hl][0].y) + (bdiM[hl][1].x + bdiM[hl][1].y);
        float r  = rp - rm + s_s[hv * 4 + 0] - s_s[hv * 4 + 1];
        float iv = ip - im + s_s[hv * 4 + 2] + s_s[hv * 4 + 3];
        float mag = sqrtf(r * r + iv * iv);
        float* Sp = &g_S[hv][n][q][b][p];
        *Sp = *Sp + mag;
    }
}

// ---------------- kernel 6: softmax over b (axis -1, size 4) ----------------
__global__ __launch_bounds__(256) void k_softmax()
{
    int idx = blockIdx.x * 256 + threadIdx.x;
    int p  = idx % P_;
    int q  = (idx / P_) % Q_;
    int hn = idx / (P_ * Q_);
    float* base = &g_S[0][0][0][0][0] + (((size_t)hn * Q_ + q) * B_) * P_ + p;
    float v0 = base[0 * P_] * TEMPF;
    float v1 = base[1 * P_] * TEMPF;
    float v2 = base[2 * P_] * TEMPF;
    float v3 = base[3 * P_] * TEMPF;
    float m = fmaxf(fmaxf(v0, v1), fmaxf(v2, v3));
    v0 = __expf(v0 - m); v1 = __expf(v1 - m); v2 = __expf(v2 - m); v3 = __expf(v3 - m);
    float inv = 1.f / (v0 + v1 + v2 + v3);
    base[0 * P_] = v0 * inv;
    base[1 * P_] = v1 * inv;
    base[2 * P_] = v2 * inv;
    base[3 * P_] = v3 * inv;
}

// ---------------- kernel 7: output aggregation (GEMM per (h,n,b,q-half)) ----------------
// grid (2 q-halves, B, H*N), block 256: tx(16)->d group 4, ty(16)->q group 4
__global__ __launch_bounds__(256) void k_out(
    const float* __restrict__ vr, const float* __restrict__ vi,
    float* __restrict__ out)
{
    int b = blockIdx.y;
    int h = blockIdx.z / N_, n = blockIdx.z % N_;
    int qh = blockIdx.x;

    __shared__ float aff_s[64][64];          // [q][p-chunk]
    __shared__ float vr_s[64][D_], vi_s[64][D_];

    int t = threadIdx.x;
    int tx = t & 15, ty = t >> 4;
    int d0 = tx * 4, lq0 = ty * 4;

    float2 cr[4][2], ci[4][2];
#pragma unroll
    for (int i = 0; i < 4; i++)
#pragma unroll
        for (int j = 0; j < 2; j++) { cr[i][j] = make_float2(0.f, 0.f); ci[i][j] = make_float2(0.f, 0.f); }

    for (int c = 0; c < 2; c++) {
        __syncthreads();
        int p0 = c * 64;
        for (int i = t; i < 64 * 64; i += 256) {
            int lq = i >> 6, pp = i & 63;
            aff_s[lq][pp] = g_S[h][n][qh * 64 + lq][b][p0 + pp];
        }
        for (int i = t; i < 64 * D_; i += 256) {
            int pp = i >> 6, d = i & 63;
            size_t off = (((size_t)n * P_ + p0 + pp) * B_ + b) * D_ + d;
            vr_s[pp][d] = vr[off];
            vi_s[pp][d] = vi[off];
        }
        __syncthreads();

#pragma unroll 4
        for (int pp = 0; pp < 64; pp++) {
            float2 v_r0 = *(const float2*)&vr_s[pp][d0];
            float2 v_r1 = *(const float2*)&vr_s[pp][d0 + 2];
            float2 v_i0 = *(const float2*)&vi_s[pp][d0];
            float2 v_i1 = *(const float2*)&vi_s[pp][d0 + 2];
#pragma unroll
            for (int i = 0; i < 4; i++) {
                float2 a2 = dup2(aff_s[lq0 + i][pp]);
                fma2(cr[i][0], a2, v_r0);  fma2(cr[i][1], a2, v_r1);
                fma2(ci[i][0], a2, v_i0);  fma2(ci[i][1], a2, v_i1);
            }
        }
    }

#pragma unroll
    for (int i = 0; i < 4; i++) {
        int qg = qh * 64 + lq0 + i;
        size_t o = (((size_t)n * Q_ + qg) * B_ + b) * (H_ * D_) + h * D_ + d0;
        *(float2*)(out + o)     = cr[i][0];
        *(float2*)(out + o + 2) = cr[i][1];
        size_t oi = o + (size_t)N_ * Q_ * B_ * H_ * D_;
        *(float2*)(out + oi)     = ci[i][0];
        *(float2*)(out + oi + 2) = ci[i][1];
    }
}

// ---------------- launch ----------------
extern "C" void kernel_launch(void* const* d_in, const int* in_sizes, int n_in,
                              void* d_out, int out_size)
{
    const float* query_r = (const float*)d_in[0];
    const float* query_i = (const float*)d_in[1];
    const float* key_r   = (const float*)d_in[2];
    const float* key_i   = (const float*)d_in[3];
    const float* val_r   = (const float*)d_in[4];
    const float* val_i   = (const float*)d_in[5];
    const float* emb_r   = (const float*)d_in[6];
    const float* emb_i   = (const float*)d_in[7];
    const float* WKr_w   = (const float*)d_in[8];
    const float* WKr_b   = (const float*)d_in[9];
    const float* WKi_w   = (const float*)d_in[10];
    const float* WKi_b   = (const float*)d_in[11];
    const float* WKRr_w  = (const float*)d_in[12];
    const float* WKRr_b  = (const float*)d_in[13];
    const float* WKRi_w  = (const float*)d_in[14];
    const float* WKRi_b  = (const float*)d_in[15];
    const float* WQr_w   = (const float*)d_in[16];
    const float* WQr_b   = (const float*)d_in[17];
    const float* WQi_w   = (const float*)d_in[18];
    const float* WQi_b   = (const float*)d_in[19];
    const float* ww_r_g  = (const float*)d_in[20];
    const float* ww_r_bt = (const float*)d_in[21];
    const float* ww_i_g  = (const float*)d_in[22];
    const float* ww_i_bt = (const float*)d_in[23];
    const float* wr_r_g  = (const float*)d_in[24];
    const float* wr_r_bt = (const float*)d_in[25];
    const float* wr_i_g  = (const float*)d_in[26];
    const float* wr_i_bt = (const float*)d_in[27];

    k_proj<<<dim3(16, H_, 2), 256>>>(key_r, key_i, query_r, query_i,
                                     WKr_w, WKr_b, WKi_w, WKi_b,
                                     WQr_w, WQr_b, WQi_w, WQi_b);
    k_norm<<<dim3(N_, H_, 4), 256>>>();
    k_tvec<<<dim3(16, H_), 256>>>(WKRr_w, WKRr_b, WKRi_w, WKRi_b,
                                  wr_r_g, wr_r_bt, wr_i_g, wr_i_bt);
    k_ac<<<dim3(4, B_, H_ * N_), 256>>>(ww_r_g, ww_r_bt, ww_i_g, ww_i_bt);
    k_bd<<<ROWS_, 256>>>(emb_r, emb_i);
    k_softmax<<<1024, 256>>>();
    k_out<<<dim3(2, B_, H_ * N_), 256>>>(val_r, val_i, (float*)d_out);
}

// round 3
// speedup vs baseline: 1.3446x; 1.0091x over previous
#include <cuda_runtime.h>
#include <math.h>

#define H_ 8
#define D_ 64
#define N_ 2
#define Q_ 128
#define P_ 128
#define B_ 4
#define ROWS_ 1024          // N_*Q_*B_ == N_*P_*B_
#define EPSF 1e-5f
#define TEMPF 30.0f

// ---------------- packed fp32x2 FMA (sm_103a FFMA2) ----------------
__device__ __forceinline__ void fma2(float2& d, float2 a, float2 b) {
    asm("fma.rn.f32x2 %0, %1, %2, %0;"
        : "+l"(reinterpret_cast<unsigned long long&>(d))
        : "l"(reinterpret_cast<unsigned long long&>(a)),
          "l"(reinterpret_cast<unsigned long long&>(b)));
}
__device__ __forceinline__ float2 dup2(float v) { return make_float2(v, v); }
__device__ __forceinline__ float2 neg2(float2 v) { return make_float2(-v.x, -v.y); }

// ---------------- scratch (device globals; no allocation) ----------------
__device__ float  g_wk_r[H_][ROWS_][D_];
__device__ float  g_wk_i[H_][ROWS_][D_];
__device__ float  g_wq_r[H_][ROWS_][D_];
__device__ float  g_wq_i[H_][ROWS_][D_];
__device__ float4 g_T [ROWS_][32][16];     // per (n,q,b): 32 t-vectors of 64 floats
__device__ float  g_S4[ROWS_][H_][4];      // bias scalars s1..s4
__device__ float  g_S [H_][N_][Q_][B_][P_];// scores -> aff

// ---------------- kernel 1: complex projections, register-tiled ----------------
// grid (32 row-tiles of 32, H, 2{key,query}), block 256 = 16x16, thread 2row x 4d
__global__ __launch_bounds__(256) void k_proj(
    const float* __restrict__ kr, const float* __restrict__ ki,
    const float* __restrict__ qr, const float* __restrict__ qi,
    const float* __restrict__ WKr, const float* __restrict__ WKrb,
    const float* __restrict__ WKi, const float* __restrict__ WKib,
    const float* __restrict__ WQr, const float* __restrict__ WQrb,
    const float* __restrict__ WQi, const float* __restrict__ WQib)
{
    int h   = blockIdx.y;
    int isQ = blockIdx.z;
    const float* xr = isQ ? qr : kr;
    const float* xi = isQ ? qi : ki;
    const float* Wr = (isQ ? WQr : WKr) + h * D_ * D_;
    const float* Wi = (isQ ? WQi : WKi) + h * D_ * D_;
    const float* br = (isQ ? WQrb : WKrb) + h * D_;
    const float* bi = (isQ ? WQib : WKib) + h * D_;
    float* outR = isQ ? &g_wq_r[h][0][0] : &g_wk_r[h][0][0];
    float* outI = isQ ? &g_wq_i[h][0][0] : &g_wk_i[h][0][0];

    __shared__ float Wr_t[D_][66];   // [e][d]
    __shared__ float Wi_t[D_][66];
    __shared__ float Xr[32][D_], Xi[32][D_];

    int t = threadIdx.x;
    for (int i = t; i < D_ * D_; i += 256) {
        int d = i >> 6, e = i & 63;
        Wr_t[e][d] = Wr[i];
        Wi_t[e][d] = Wi[i];
    }
    int row0 = blockIdx.x * 32;
    const float4* xr4 = (const float4*)(xr + (size_t)row0 * D_);
    const float4* xi4 = (const float4*)(xi + (size_t)row0 * D_);
    for (int i = t; i < 32 * D_ / 4; i += 256) {
        ((float4*)Xr)[i] = xr4[i];
        ((float4*)Xi)[i] = xi4[i];
    }
    __syncthreads();

    int tx = t & 15, ty = t >> 4;
    int d0 = tx * 4, r0 = ty * 2;

    float2 ar[2][2], ai[2][2];
#pragma unroll
    for (int i = 0; i < 2; i++)
#pragma unroll
        for (int j = 0; j < 2; j++) { ar[i][j] = make_float2(0.f, 0.f); ai[i][j] = make_float2(0.f, 0.f); }

#pragma unroll 4
    for (int e = 0; e < 64; e++) {
        float2 wr0 = *(const float2*)&Wr_t[e][d0];
        float2 wr1 = *(const float2*)&Wr_t[e][d0 + 2];
        float2 wi0 = *(const float2*)&Wi_t[e][d0];
        float2 wi1 = *(const float2*)&Wi_t[e][d0 + 2];
        float2 nwi0 = neg2(wi0), nwi1 = neg2(wi1);
#pragma unroll
        for (int i = 0; i < 2; i++) {
            float2 v2r = dup2(Xr[r0 + i][e]);
            float2 v2i = dup2(Xi[r0 + i][e]);
            fma2(ar[i][0], v2r, wr0);  fma2(ar[i][0], v2i, nwi0);
            fma2(ar[i][1], v2r, wr1);  fma2(ar[i][1], v2i, nwi1);
            fma2(ai[i][0], v2r, wi0);  fma2(ai[i][0], v2i, wr0);
            fma2(ai[i][1], v2r, wi1);  fma2(ai[i][1], v2i, wr1);
        }
    }

    float2 bR0 = *(const float2*)&br[d0];
    float2 bR1 = *(const float2*)&br[d0 + 2];
    float2 bI0 = *(const float2*)&bi[d0];
    float2 bI1 = *(const float2*)&bi[d0 + 2];
#pragma unroll
    for (int i = 0; i < 2; i++) {
        ar[i][0].x += bR0.x - bI0.x;  ar[i][0].y += bR0.y - bI0.y;
        ar[i][1].x += bR1.x - bI1.x;  ar[i][1].y += bR1.y - bI1.y;
        ai[i][0].x += bR0.x + bI0.x;  ai[i][0].y += bR0.y + bI0.y;
        ai[i][1].x += bR1.x + bI1.x;  ai[i][1].y += bR1.y + bI1.y;
        float2* oR = (float2*)(outR + (size_t)(row0 + r0 + i) * D_ + d0);
        float2* oI = (float2*)(outI + (size_t)(row0 + r0 + i) * D_ + d0);
        oR[0] = ar[i][0];  oR[1] = ar[i][1];
        oI[0] = ai[i][0];  oI[1] = ai[i][1];
    }
}

// ---------------- kernel 2: instance-norm over (p,b) per (h,n,d) ----------------
// grid (N_, H_, 4), block 512
__global__ __launch_bounds__(512) void k_norm()
{
    int n = blockIdx.x, h = blockIdx.y, a = blockIdx.z;
    float* base;
    if      (a == 0) base = &g_wk_r[0][0][0];
    else if (a == 1) base = &g_wk_i[0][0][0];
    else if (a == 2) base = &g_wq_r[0][0][0];
    else             base = &g_wq_i[0][0][0];
    float* x = base + ((size_t)h * ROWS_ + (size_t)n * 512) * D_;

    int t = threadIdx.x;
    int d = t & 63, c = t >> 6;       // 8 chunks of 64 rows
    float s = 0.f, s2 = 0.f;
    for (int r = c * 64; r < (c + 1) * 64; r++) {
        float v = x[r * 64 + d];
        s += v; s2 += v * v;
    }
    __shared__ float Ss[8][64], S2s[8][64];
    __shared__ float mean_s[64], rstd_s[64];
    Ss[c][d] = s; S2s[c][d] = s2;
    __syncthreads();
    if (t < 64) {
        float sum = 0.f, sum2 = 0.f;
#pragma unroll
        for (int cc = 0; cc < 8; cc++) { sum += Ss[cc][t]; sum2 += S2s[cc][t]; }
        float m   = sum * (1.f / 512.f);
        float var = sum2 * (1.f / 512.f) - m * m;
        mean_s[t] = m;
        rstd_s[t] = rsqrtf(var + EPSF);
    }
    __syncthreads();
    for (int i = t; i < 512 * 64; i += 512) {
        int dd = i & 63;
        x[i] = (x[i] - mean_s[dd]) * rstd_s[dd];
    }
}

// ---------------- kernel 3: t-vectors (GEMM) + bias scalars ----------------
// grid (32 row-tiles of 32, H), block 256 = 16x16, thread 2row x 4e, 4 outputs
__global__ __launch_bounds__(256) void k_tvec(
    const float* __restrict__ WKRr, const float* __restrict__ WKRrb,
    const float* __restrict__ WKRi, const float* __restrict__ WKRib,
    const float* __restrict__ wr_r_g, const float* __restrict__ wr_r_bt,
    const float* __restrict__ wr_i_g, const float* __restrict__ wr_i_bt)
{
    int h = blockIdx.y;
    int pt0 = blockIdx.x * 32;
    __shared__ float Ur[32][D_], Ui[32][D_];
    __shared__ float Wr_s[64][66], Wi_s[64][66];   // [d][e]
    __shared__ float bm_s[64], bp_s[64];

    int t = threadIdx.x;
    const float* Wr = WKRr + h * D_ * D_;
    const float* Wi = WKRi + h * D_ * D_;
    for (int i = t; i < D_ * D_; i += 256) {
        int dd = i >> 6, e = i & 63;
        Wr_s[dd][e] = Wr[i];
        Wi_s[dd][e] = Wi[i];
    }
    for (int i = t; i < 32 * D_; i += 256) {
        int l = i >> 6, d = i & 63;
        float yr = g_wq_r[h][pt0 + l][d];
        float yi = g_wq_i[h][pt0 + l][d];
        Ur[l][d] = yr * wr_r_g[h * D_ + d] + wr_r_bt[h * D_ + d];
        Ui[l][d] = yi * wr_i_g[h * D_ + d] + wr_i_bt[h * D_ + d];
    }
    if (t < 64) {
        float brv = WKRrb[h * D_ + t], biv = WKRib[h * D_ + t];
        bm_s[t] = brv - biv;
        bp_s[t] = brv + biv;
    }
    __syncthreads();

    int tx = t & 15, ty = t >> 4;
    int e0 = tx * 4, r0 = ty * 2;

    float2 t1[2][2], t2[2][2], t3[2][2], t4[2][2];
#pragma unroll
    for (int i = 0; i < 2; i++)
#pragma unroll
        for (int j = 0; j < 2; j++) {
            t1[i][j] = make_float2(0.f, 0.f); t2[i][j] = make_float2(0.f, 0.f);
            t3[i][j] = make_float2(0.f, 0.f); t4[i][j] = make_float2(0.f, 0.f);
        }

#pragma unroll 4
    for (int dd = 0; dd < 64; dd++) {
        float2 wr0 = *(const float2*)&Wr_s[dd][e0];
        float2 wr1 = *(const float2*)&Wr_s[dd][e0 + 2];
        float2 wi0 = *(const float2*)&Wi_s[dd][e0];
        float2 wi1 = *(const float2*)&Wi_s[dd][e0 + 2];
#pragma unroll
        for (int i = 0; i < 2; i++) {
            float2 u2r = dup2(Ur[r0 + i][dd]);
            float2 u2i = dup2(Ui[r0 + i][dd]);
            fma2(t1[i][0], u2r, wr0);  fma2(t1[i][1], u2r, wr1);
            fma2(t2[i][0], u2r, wi0);  fma2(t2[i][1], u2r, wi1);
            fma2(t3[i][0], u2i, wr0);  fma2(t3[i][1], u2i, wr1);
            fma2(t4[i][0], u2i, wi0);  fma2(t4[i][1], u2i, wi1);
        }
    }

#pragma unroll
    for (int i = 0; i < 2; i++) {
        float* base = (float*)&g_T[pt0 + r0 + i][h * 4][0];   // 4 vecs x 64 floats
        *(float2*)(base +   0 + e0) = t1[i][0];  *(float2*)(base +   0 + e0 + 2) = t1[i][1];
        *(float2*)(base +  64 + e0) = t2[i][0];  *(float2*)(base +  64 + e0 + 2) = t2[i][1];
        *(float2*)(base + 128 + e0) = t3[i][0];  *(float2*)(base + 128 + e0 + 2) = t3[i][1];
        *(float2*)(base + 192 + e0) = t4[i][0];  *(float2*)(base + 192 + e0 + 2) = t4[i][1];
    }

    if (tx == 0) {
#pragma unroll
        for (int i = 0; i < 2; i++) {
            float s1 = 0.f, s2v = 0.f, s3 = 0.f, s4 = 0.f;
            for (int dd = 0; dd < 64; dd++) {
                float u_r = Ur[r0 + i][dd], u_i = Ui[r0 + i][dd];
                float bm = bm_s[dd], bp = bp_s[dd];
                s1 += bm * u_r;  s2v += bp * u_i;
                s3 += bm * u_i;  s4 += bp * u_r;
            }
            int pt = pt0 + r0 + i;
            g_S4[pt][h][0] = s1;  g_S4[pt][h][1] = s2v;
            g_S4[pt][h][2] = s3;  g_S4[pt][h][3] = s4;
        }
    }
}

// ---------------- kernel 4: AC magnitudes, register-tiled complex GEMM ----------------
// grid (8 = 2 p-halves x 4 q-quarters, B, H*N), block 256: tx(32)->p, ty(8)->4q
__global__ __launch_bounds__(256) void k_ac(
    const float* __restrict__ ww_r_g, const float* __restrict__ ww_r_bt,
    const float* __restrict__ ww_i_g, const float* __restrict__ ww_i_bt)
{
    int b = blockIdx.y;
    int h = blockIdx.z / N_, n = blockIdx.z % N_;
    int pt = blockIdx.x & 1, qt = blockIdx.x >> 1;
    int q0 = qt * 32, p0 = pt * 64;

    __shared__ float wqrT[64][34], wqiT[64][34];     // [d][q], q-pairs contiguous
    __shared__ float wkrT[64][66], wkiT[64][66];     // [d][p]

    int t = threadIdx.x;
    for (int i = t; i < 32 * D_; i += 256) {
        int q = i >> 6, d = i & 63;
        int row = (n * Q_ + q0 + q) * B_ + b;
        float yr = g_wq_r[h][row][d];
        float yi = g_wq_i[h][row][d];
        wqrT[d][q] = yr * ww_r_g[h * D_ + d] + ww_r_bt[h * D_ + d];
        wqiT[d][q] = yi * ww_i_g[h * D_ + d] + ww_i_bt[h * D_ + d];
    }
    for (int i = t; i < 64 * D_; i += 256) {
        int p = i >> 6, d = i & 63;
        int row = (n * P_ + p0 + p) * B_ + b;
        wkrT[d][p] = g_wk_r[h][row][d];
        wkiT[d][p] = g_wk_i[h][row][d];
    }
    __syncthreads();

    int tx = t & 31, ty = t >> 5;
    int lq0 = ty * 4;

    float2 accR[2][2], accI[2][2];   // [q-pair ii][p j], p_j = tx + 32*j
#pragma unroll
    for (int ii = 0; ii < 2; ii++)
#pragma unroll
        for (int j = 0; j < 2; j++) { accR[ii][j] = make_float2(0.f, 0.f); accI[ii][j] = make_float2(0.f, 0.f); }

#pragma unroll 4
    for (int d = 0; d < 64; d++) {
        float2 qr2[2], qi2[2];
        qr2[0] = *(const float2*)&wqrT[d][lq0];
        qr2[1] = *(const float2*)&wqrT[d][lq0 + 2];
        qi2[0] = *(const float2*)&wqiT[d][lq0];
        qi2[1] = *(const float2*)&wqiT[d][lq0 + 2];
        float kr_[2], ki_[2];
#pragma unroll
        for (int j = 0; j < 2; j++) { kr_[j] = wkrT[d][tx + 32 * j]; ki_[j] = wkiT[d][tx + 32 * j]; }
#pragma unroll
        for (int ii = 0; ii < 2; ii++) {
            float2 nqi2 = neg2(qi2[ii]);
#pragma unroll
            for (int j = 0; j < 2; j++) {
                float2 kr2 = dup2(kr_[j]);
                float2 ki2 = dup2(ki_[j]);
                fma2(accR[ii][j], qr2[ii], kr2);  fma2(accR[ii][j], nqi2, ki2);
                fma2(accI[ii][j], qr2[ii], ki2);  fma2(accI[ii][j], qi2[ii], kr2);
            }
        }
    }

#pragma unroll
    for (int ii = 0; ii < 2; ii++)
#pragma unroll
        for (int j = 0; j < 2; j++) {
            int qg = q0 + lq0 + 2 * ii;
            int p  = p0 + tx + 32 * j;
            float r0v = accR[ii][j].x, i0v = accI[ii][j].x;
            float r1v = accR[ii][j].y, i1v = accI[ii][j].y;
            g_S[h][n][qg][b][p]     = sqrtf(r0v * r0v + i0v * i0v);
            g_S[h][n][qg + 1][b][p] = sqrtf(r1v * r1v + i1v * i1v);
        }
}

// ---------------- kernel 5: BD (hot loop), f32x2, 256 threads (h-split) ----------------
__global__ __launch_bounds__(256) void k_bd(
    const float* __restrict__ emb_r, const float* __restrict__ emb_i)
{
    int pt = blockIdx.x;
    int b  = pt % B_;
    int q  = (pt / B_) % Q_;
    int n  = pt / (B_ * Q_);

    __shared__ float4 T_s[32][16];
    __shared__ float  s_s[32];
    int t = threadIdx.x;
    const float4* Tg = &g_T[pt][0][0];
    for (int i = t; i < 32 * 16; i += 256) ((float4*)T_s)[i] = Tg[i];
    if (t < 32) s_s[t] = ((const float*)&g_S4[pt][0][0])[t];
    __syncthreads();

    int p  = t & 127;
    int hh = t >> 7;           // 0/1: handles h in [hh*4, hh*4+4)
    int h0 = hh * 4;

    const float4* rRR = (const float4*)(emb_r + ((((size_t)n * Q_ + q) * P_ + p) * B_ + b) * D_);
    const float4* rIR = (const float4*)(emb_i + ((((size_t)n * Q_ + q) * P_ + p) * B_ + b) * D_);
    const float4* rRC = (const float4*)(emb_r + ((((size_t)n * Q_ + p) * P_ + q) * B_ + b) * D_);
    const float4* rIC = (const float4*)(emb_i + ((((size_t)n * Q_ + p) * P_ + q) * B_ + b) * D_);

    float2 bdrP[4][2], bdrM[4][2], bdiP[4][2], bdiM[4][2];
#pragma unroll
    for (int hl = 0; hl < 4; hl++)
#pragma unroll
        for (int j = 0; j < 2; j++) {
            bdrP[hl][j] = make_float2(0.f, 0.f); bdrM[hl][j] = make_float2(0.f, 0.f);
            bdiP[hl][j] = make_float2(0.f, 0.f); bdiM[hl][j] = make_float2(0.f, 0.f);
        }

#pragma unroll 2
    for (int d4 = 0; d4 < 16; d4++) {
        float4 er = __ldg(rRR + d4);
        float4 ei = __ldg(rIR + d4);
        float4 fr = __ldg(rRC + d4);
        float4 fi = __ldg(rIC + d4);
        float2 er_a = make_float2(er.x, er.y), er_b = make_float2(er.z, er.w);
        float2 ei_a = make_float2(ei.x, ei.y), ei_b = make_float2(ei.z, ei.w);
        float2 fr_a = make_float2(fr.x, fr.y), fr_b = make_float2(fr.z, fr.w);
        float2 fi_a = make_float2(fi.x, fi.y), fi_b = make_float2(fi.z, fi.w);
#pragma unroll
        for (int hl = 0; hl < 4; hl++) {
            int hv = h0 + hl;
            float4 T1 = T_s[4 * hv + 0][d4];
            float4 T2 = T_s[4 * hv + 1][d4];
            float4 T3 = T_s[4 * hv + 2][d4];
            float4 T4 = T_s[4 * hv + 3][d4];
            float2 T1a = make_float2(T1.x, T1.y), T1b = make_float2(T1.z, T1.w);
            float2 T2a = make_float2(T2.x, T2.y), T2b = make_float2(T2.z, T2.w);
            float2 T3a = make_float2(T3.x, T3.y), T3b = make_float2(T3.z, T3.w);
            float2 T4a = make_float2(T4.x, T4.y), T4b = make_float2(T4.z, T4.w);
            fma2(bdrP[hl][0], er_a, T1a);  fma2(bdrP[hl][1], er_b, T1b);
            fma2(bdrM[hl][0], ei_a, T2a);  fma2(bdrM[hl][1], ei_b, T2b);
            fma2(bdrM[hl][0], fr_a, T4a);  fma2(bdrM[hl][1], fr_b, T4b);
            fma2(bdrM[hl][0], fi_a, T3a);  fma2(bdrM[hl][1], fi_b, T3b);
            fma2(bdiP[hl][0], er_a, T3a);  fma2(bdiP[hl][1], er_b, T3b);
            fma2(bdiP[hl][0], fr_a, T2a);  fma2(bdiP[hl][1], fr_b, T2b);
            fma2(bdiP[hl][0], fi_a, T1a);  fma2(bdiP[hl][1], fi_b, T1b);
            fma2(bdiM[hl][0], ei_a, T4a);  fma2(bdiM[hl][1], ei_b, T4b);
        }
    }

#pragma unroll
    for (int hl = 0; hl < 4; hl++) {
        int hv = h0 + hl;
        float rp = (bdrP[hl][0].x + bdrP[hl][0].y) + (bdrP[hl][1].x + bdrP[hl][1].y);
        float rm = (bdrM[hl][0].x + bdrM[hl][0].y) + (bdrM[hl][1].x + bdrM[hl][1].y);
        float ip = (bdiP[hl][0].x + bdiP[hl][0].y) + (bdiP[hl][1].x + bdiP[hl][1].y);
        float im = (bdiM[hl][0].x + bdiM[hl][0].y) + (bdiM[hl][1].x + bdiM[hl][1].y);
        float r  = rp - rm + s_s[hv * 4 + 0] - s_s[hv * 4 + 1];
        float iv = ip - im + s_s[hv * 4 + 2] + s_s[hv * 4 + 3];
        float mag = sqrtf(r * r + iv * iv);
        float* Sp = &g_S[hv][n][q][b][p];
        *Sp = *Sp + mag;
    }
}

// ---------------- kernel 6: softmax over b (axis -1, size 4) ----------------
__global__ __launch_bounds__(256) void k_softmax()
{
    int idx = blockIdx.x * 256 + threadIdx.x;
    int p  = idx % P_;
    int q  = (idx / P_) % Q_;
    int hn = idx / (P_ * Q_);
    float* base = &g_S[0][0][0][0][0] + (((size_t)hn * Q_ + q) * B_) * P_ + p;
    float v0 = base[0 * P_] * TEMPF;
    float v1 = base[1 * P_] * TEMPF;
    float v2 = base[2 * P_] * TEMPF;
    float v3 = base[3 * P_] * TEMPF;
    float m = fmaxf(fmaxf(v0, v1), fmaxf(v2, v3));
    v0 = __expf(v0 - m); v1 = __expf(v1 - m); v2 = __expf(v2 - m); v3 = __expf(v3 - m);
    float inv = 1.f / (v0 + v1 + v2 + v3);
    base[0 * P_] = v0 * inv;
    base[1 * P_] = v1 * inv;
    base[2 * P_] = v2 * inv;
    base[3 * P_] = v3 * inv;
}

// ---------------- kernel 7: output aggregation (GEMM per (h,n,b,q-tile)) ----------------
// grid (4 q-tiles of 32, B, H*N), block 256: tx(16)->4d, ty(16)->2q
__global__ __launch_bounds__(256) void k_out(
    const float* __restrict__ vr, const float* __restrict__ vi,
    float* __restrict__ out)
{
    int b = blockIdx.y;
    int h = blockIdx.z / N_, n = blockIdx.z % N_;
    int q0 = blockIdx.x * 32;

    __shared__ float aff_s[32][64];          // [q][p-chunk]
    __shared__ float vr_s[64][D_], vi_s[64][D_];

    int t = threadIdx.x;
    int tx = t & 15, ty = t >> 4;
    int d0 = tx * 4, lq0 = ty * 2;

    float2 cr[2][2], ci[2][2];
#pragma unroll
    for (int i = 0; i < 2; i++)
#pragma unroll
        for (int j = 0; j < 2; j++) { cr[i][j] = make_float2(0.f, 0.f); ci[i][j] = make_float2(0.f, 0.f); }

    for (int c = 0; c < 2; c++) {
        __syncthreads();
        int p0 = c * 64;
        for (int i = t; i < 32 * 64; i += 256) {
            int lq = i >> 6, pp = i & 63;
            aff_s[lq][pp] = g_S[h][n][q0 + lq][b][p0 + pp];
        }
        for (int i = t; i < 64 * D_; i += 256) {
            int pp = i >> 6, d = i & 63;
            size_t off = (((size_t)n * P_ + p0 + pp) * B_ + b) * D_ + d;
            vr_s[pp][d] = vr[off];
            vi_s[pp][d] = vi[off];
        }
        __syncthreads();

#pragma unroll 4
        for (int pp = 0; pp < 64; pp++) {
            float2 v_r0 = *(const float2*)&vr_s[pp][d0];
            float2 v_r1 = *(const float2*)&vr_s[pp][d0 + 2];
            float2 v_i0 = *(const float2*)&vi_s[pp][d0];
            float2 v_i1 = *(const float2*)&vi_s[pp][d0 + 2];
#pragma unroll
            for (int i = 0; i < 2; i++) {
                float2 a2 = dup2(aff_s[lq0 + i][pp]);
                fma2(cr[i][0], a2, v_r0);  fma2(cr[i][1], a2, v_r1);
                fma2(ci[i][0], a2, v_i0);  fma2(ci[i][1], a2, v_i1);
            }
        }
    }

#pragma unroll
    for (int i = 0; i < 2; i++) {
        int qg = q0 + lq0 + i;
        size_t o = (((size_t)n * Q_ + qg) * B_ + b) * (H_ * D_) + h * D_ + d0;
        *(float2*)(out + o)     = cr[i][0];
        *(float2*)(out + o + 2) = cr[i][1];
        size_t oi = o + (size_t)N_ * Q_ * B_ * H_ * D_;
        *(float2*)(out + oi)     = ci[i][0];
        *(float2*)(out + oi + 2) = ci[i][1];
    }
}

// ---------------- launch ----------------
extern "C" void kernel_launch(void* const* d_in, const int* in_sizes, int n_in,
                              void* d_out, int out_size)
{
    const float* query_r = (const float*)d_in[0];
    const float* query_i = (const float*)d_in[1];
    const float* key_r   = (const float*)d_in[2];
    const float* key_i   = (const float*)d_in[3];
    const float* val_r   = (const float*)d_in[4];
    const float* val_i   = (const float*)d_in[5];
    const float* emb_r   = (const float*)d_in[6];
    const float* emb_i   = (const float*)d_in[7];
    const float* WKr_w   = (const float*)d_in[8];
    const float* WKr_b   = (const float*)d_in[9];
    const float* WKi_w   = (const float*)d_in[10];
    const float* WKi_b   = (const float*)d_in[11];
    const float* WKRr_w  = (const float*)d_in[12];
    const float* WKRr_b  = (const float*)d_in[13];
    const float* WKRi_w  = (const float*)d_in[14];
    const float* WKRi_b  = (const float*)d_in[15];
    const float* WQr_w   = (const float*)d_in[16];
    const float* WQr_b   = (const float*)d_in[17];
    const float* WQi_w   = (const float*)d_in[18];
    const float* WQi_b   = (const float*)d_in[19];
    const float* ww_r_g  = (const float*)d_in[20];
    const float* ww_r_bt = (const float*)d_in[21];
    const float* ww_i_g  = (const float*)d_in[22];
    const float* ww_i_bt = (const float*)d_in[23];
    const float* wr_r_g  = (const float*)d_in[24];
    const float* wr_r_bt = (const float*)d_in[25];
    const float* wr_i_g  = (const float*)d_in[26];
    const float* wr_i_bt = (const float*)d_in[27];

    k_proj<<<dim3(32, H_, 2), 256>>>(key_r, key_i, query_r, query_i,
                                     WKr_w, WKr_b, WKi_w, WKi_b,
                                     WQr_w, WQr_b, WQi_w, WQi_b);
    k_norm<<<dim3(N_, H_, 4), 512>>>();
    k_tvec<<<dim3(32, H_), 256>>>(WKRr_w, WKRr_b, WKRi_w, WKRi_b,
                                  wr_r_g, wr_r_bt, wr_i_g, wr_i_bt);
    k_ac<<<dim3(8, B_, H_ * N_), 256>>>(ww_r_g, ww_r_bt, ww_i_g, ww_i_bt);
    k_bd<<<ROWS_, 256>>>(emb_r, emb_i);
    k_softmax<<<1024, 256>>>();
    k_out<<<dim3(4, B_, H_ * N_), 256>>>(val_r, val_i, (float*)d_out);
}

// round 5
// speedup vs baseline: 1.3737x; 1.0216x over previous
#include <cuda_runtime.h>
#include <math.h>

#define H_ 8
#define D_ 64
#define N_ 2
#define Q_ 128
#define P_ 128
#define B_ 4
#define ROWS_ 1024          // N_*Q_*B_ == N_*P_*B_
#define EPSF 1e-5f
#define TEMPF 30.0f

// ---------------- packed fp32x2 FMA (sm_103a FFMA2) ----------------
__device__ __forceinline__ void fma2(float2& d, float2 a, float2 b) {
    asm("fma.rn.f32x2 %0, %1, %2, %0;"
        : "+l"(reinterpret_cast<unsigned long long&>(d))
        : "l"(reinterpret_cast<unsigned long long&>(a)),
          "l"(reinterpret_cast<unsigned long long&>(b)));
}
__device__ __forceinline__ float2 dup2(float v) { return make_float2(v, v); }
__device__ __forceinline__ float2 neg2(float2 v) { return make_float2(-v.x, -v.y); }

// ---------------- scratch (device globals; no allocation) ----------------
__device__ float  g_wk_r[H_][ROWS_][D_];   // RAW projections (pre-norm)
__device__ float  g_wk_i[H_][ROWS_][D_];
__device__ float  g_wq_r[H_][ROWS_][D_];
__device__ float  g_wq_i[H_][ROWS_][D_];
__device__ float  g_mean[4][H_][N_][64];   // a: 0 wk_r, 1 wk_i, 2 wq_r, 3 wq_i
__device__ float  g_rstd[4][H_][N_][64];
__device__ float4 g_T [ROWS_][32][16];     // per (n,q,b): 32 t-vectors of 64 floats
__device__ float  g_S4[ROWS_][H_][4];      // bias scalars s1..s4
__device__ float  g_S [H_][N_][Q_][B_][P_];// AC scores -> aff
__device__ float  g_S2[H_][N_][Q_][B_][P_];// BD magnitudes

// ---------------- kernel 1: complex projections, register-tiled ----------------
// grid (32 row-tiles of 32, H, 2{key,query}), block 256 = 16x16, thread 2row x 4d
__global__ __launch_bounds__(256) void k_proj(
    const float* __restrict__ kr, const float* __restrict__ ki,
    const float* __restrict__ qr, const float* __restrict__ qi,
    const float* __restrict__ WKr, const float* __restrict__ WKrb,
    const float* __restrict__ WKi, const float* __restrict__ WKib,
    const float* __restrict__ WQr, const float* __restrict__ WQrb,
    const float* __restrict__ WQi, const float* __restrict__ WQib)
{
    int h   = blockIdx.y;
    int isQ = blockIdx.z;
    const float* xr = isQ ? qr : kr;
    const float* xi = isQ ? qi : ki;
    const float* Wr = (isQ ? WQr : WKr) + h * D_ * D_;
    const float* Wi = (isQ ? WQi : WKi) + h * D_ * D_;
    const float* br = (isQ ? WQrb : WKrb) + h * D_;
    const float* bi = (isQ ? WQib : WKib) + h * D_;
    float* outR = isQ ? &g_wq_r[h][0][0] : &g_wk_r[h][0][0];
    float* outI = isQ ? &g_wq_i[h][0][0] : &g_wk_i[h][0][0];

    __shared__ float Wr_t[D_][66];   // [e][d]
    __shared__ float Wi_t[D_][66];
    __shared__ float Xr[32][D_], Xi[32][D_];

    int t = threadIdx.x;
    for (int i = t; i < D_ * D_; i += 256) {
        int d = i >> 6, e = i & 63;
        Wr_t[e][d] = Wr[i];
        Wi_t[e][d] = Wi[i];
    }
    int row0 = blockIdx.x * 32;
    const float4* xr4 = (const float4*)(xr + (size_t)row0 * D_);
    const float4* xi4 = (const float4*)(xi + (size_t)row0 * D_);
    for (int i = t; i < 32 * D_ / 4; i += 256) {
        ((float4*)Xr)[i] = xr4[i];
        ((float4*)Xi)[i] = xi4[i];
    }
    __syncthreads();

    int tx = t & 15, ty = t >> 4;
    int d0 = tx * 4, r0 = ty * 2;

    float2 ar[2][2], ai[2][2];
#pragma unroll
    for (int i = 0; i < 2; i++)
#pragma unroll
        for (int j = 0; j < 2; j++) { ar[i][j] = make_float2(0.f, 0.f); ai[i][j] = make_float2(0.f, 0.f); }

#pragma unroll 4
    for (int e = 0; e < 64; e++) {
        float2 wr0 = *(const float2*)&Wr_t[e][d0];
        float2 wr1 = *(const float2*)&Wr_t[e][d0 + 2];
        float2 wi0 = *(const float2*)&Wi_t[e][d0];
        float2 wi1 = *(const float2*)&Wi_t[e][d0 + 2];
        float2 nwi0 = neg2(wi0), nwi1 = neg2(wi1);
#pragma unroll
        for (int i = 0; i < 2; i++) {
            float2 v2r = dup2(Xr[r0 + i][e]);
            float2 v2i = dup2(Xi[r0 + i][e]);
            fma2(ar[i][0], v2r, wr0);  fma2(ar[i][0], v2i, nwi0);
            fma2(ar[i][1], v2r, wr1);  fma2(ar[i][1], v2i, nwi1);
            fma2(ai[i][0], v2r, wi0);  fma2(ai[i][0], v2i, wr0);
            fma2(ai[i][1], v2r, wi1);  fma2(ai[i][1], v2i, wr1);
        }
    }

    float2 bR0 = *(const float2*)&br[d0];
    float2 bR1 = *(const float2*)&br[d0 + 2];
    float2 bI0 = *(const float2*)&bi[d0];
    float2 bI1 = *(const float2*)&bi[d0 + 2];
#pragma unroll
    for (int i = 0; i < 2; i++) {
        ar[i][0].x += bR0.x - bI0.x;  ar[i][0].y += bR0.y - bI0.y;
        ar[i][1].x += bR1.x - bI1.x;  ar[i][1].y += bR1.y - bI1.y;
        ai[i][0].x += bR0.x + bI0.x;  ai[i][0].y += bR0.y + bI0.y;
        ai[i][1].x += bR1.x + bI1.x;  ai[i][1].y += bR1.y + bI1.y;
        float2* oR = (float2*)(outR + (size_t)(row0 + r0 + i) * D_ + d0);
        float2* oI = (float2*)(outI + (size_t)(row0 + r0 + i) * D_ + d0);
        oR[0] = ar[i][0];  oR[1] = ar[i][1];
        oI[0] = ai[i][0];  oI[1] = ai[i][1];
    }
}

// ---------------- kernel 2: instance-norm STATS only (no normalize pass) ----------------
// grid (N_, H_, 4), block 512
__global__ __launch_bounds__(512) void k_stats()
{
    int n = blockIdx.x, h = blockIdx.y, a = blockIdx.z;
    const float* base;
    if      (a == 0) base = &g_wk_r[0][0][0];
    else if (a == 1) base = &g_wk_i[0][0][0];
    else if (a == 2) base = &g_wq_r[0][0][0];
    else             base = &g_wq_i[0][0][0];
    const float* x = base + ((size_t)h * ROWS_ + (size_t)n * 512) * D_;

    int t = threadIdx.x;
    int d = t & 63, c = t >> 6;       // 8 chunks of 64 rows
    float s = 0.f, s2 = 0.f;
    for (int r = c * 64; r < (c + 1) * 64; r++) {
        float v = x[r * 64 + d];
        s += v; s2 += v * v;
    }
    __shared__ float Ss[8][64], S2s[8][64];
    Ss[c][d] = s; S2s[c][d] = s2;
    __syncthreads();
    if (t < 64) {
        float sum = 0.f, sum2 = 0.f;
#pragma unroll
        for (int cc = 0; cc < 8; cc++) { sum += Ss[cc][t]; sum2 += S2s[cc][t]; }
        float m   = sum * (1.f / 512.f);
        float var = sum2 * (1.f / 512.f) - m * m;
        g_mean[a][h][n][t] = m;
        g_rstd[a][h][n][t] = rsqrtf(var + EPSF);
    }
}

// ---------------- kernel 3: t-vectors (GEMM) + bias scalars (norm folded) ----------------
// grid (32 row-tiles of 32, H), block 256 = 16x16
__global__ __launch_bounds__(256) void k_tvec(
    const float* __restrict__ WKRr, const float* __restrict__ WKRrb,
    const float* __restrict__ WKRi, const float* __restrict__ WKRib,
    const float* __restrict__ wr_r_g, const float* __restrict__ wr_r_bt,
    const float* __restrict__ wr_i_g, const float* __restrict__ wr_i_bt)
{
    int h = blockIdx.y;
    int pt0 = blockIdx.x * 32;
    int n = pt0 >> 9;                 // rows 0..511 -> n=0, 512.. -> n=1
    __shared__ float Ur[32][D_], Ui[32][D_];
    __shared__ float Wr_s[64][66], Wi_s[64][66];   // [d][e]
    __shared__ float bm_s[64], bp_s[64];
    __shared__ float Ar_s[64], Cr_s[64], Ai_s[64], Ci_s[64];

    int t = threadIdx.x;
    const float* Wr = WKRr + h * D_ * D_;
    const float* Wi = WKRi + h * D_ * D_;
    for (int i = t; i < D_ * D_; i += 256) {
        int dd = i >> 6, e = i & 63;
        Wr_s[dd][e] = Wr[i];
        Wi_s[dd][e] = Wi[i];
    }
    if (t < 64) {
        float brv = WKRrb[h * D_ + t], biv = WKRib[h * D_ + t];
        bm_s[t] = brv - biv;
        bp_s[t] = brv + biv;
        // wr-affine folded with instance-norm of raw wq
        float m2 = g_mean[2][h][n][t], r2 = g_rstd[2][h][n][t];
        float m3 = g_mean[3][h][n][t], r3 = g_rstd[3][h][n][t];
        float gr = wr_r_g[h * 64 + t], btr = wr_r_bt[h * 64 + t];
        float gi = wr_i_g[h * 64 + t], bti = wr_i_bt[h * 64 + t];
        Ar_s[t] = r2 * gr;  Cr_s[t] = btr - m2 * r2 * gr;
        Ai_s[t] = r3 * gi;  Ci_s[t] = bti - m3 * r3 * gi;
    }
    __syncthreads();
    for (int i = t; i < 32 * D_; i += 256) {
        int l = i >> 6, d = i & 63;
        Ur[l][d] = g_wq_r[h][pt0 + l][d] * Ar_s[d] + Cr_s[d];
        Ui[l][d] = g_wq_i[h][pt0 + l][d] * Ai_s[d] + Ci_s[d];
    }
    __syncthreads();

    int tx = t & 15, ty = t >> 4;
    int e0 = tx * 4, r0 = ty * 2;

    float2 t1[2][2], t2[2][2], t3[2][2], t4[2][2];
#pragma unroll
    for (int i = 0; i < 2; i++)
#pragma unroll
        for (int j = 0; j < 2; j++) {
            t1[i][j] = make_float2(0.f, 0.f); t2[i][j] = make_float2(0.f, 0.f);
            t3[i][j] = make_float2(0.f, 0.f); t4[i][j] = make_float2(0.f, 0.f);
        }

#pragma unroll 4
    for (int dd = 0; dd < 64; dd++) {
        float2 wr0 = *(const float2*)&Wr_s[dd][e0];
        float2 wr1 = *(const float2*)&Wr_s[dd][e0 + 2];
        float2 wi0 = *(const float2*)&Wi_s[dd][e0];
        float2 wi1 = *(const float2*)&Wi_s[dd][e0 + 2];
#pragma unroll
        for (int i = 0; i < 2; i++) {
            float2 u2r = dup2(Ur[r0 + i][dd]);
            float2 u2i = dup2(Ui[r0 + i][dd]);
            fma2(t1[i][0], u2r, wr0);  fma2(t1[i][1], u2r, wr1);
            fma2(t2[i][0], u2r, wi0);  fma2(t2[i][1], u2r, wi1);
            fma2(t3[i][0], u2i, wr0);  fma2(t3[i][1], u2i, wr1);
            fma2(t4[i][0], u2i, wi0);  fma2(t4[i][1], u2i, wi1);
        }
    }

#pragma unroll
    for (int i = 0; i < 2; i++) {
        float* base = (float*)&g_T[pt0 + r0 + i][h * 4][0];   // 4 vecs x 64 floats
        *(float2*)(base +   0 + e0) = t1[i][0];  *(float2*)(base +   0 + e0 + 2) = t1[i][1];
        *(float2*)(base +  64 + e0) = t2[i][0];  *(float2*)(base +  64 + e0 + 2) = t2[i][1];
        *(float2*)(base + 128 + e0) = t3[i][0];  *(float2*)(base + 128 + e0 + 2) = t3[i][1];
        *(float2*)(base + 192 + e0) = t4[i][0];  *(float2*)(base + 192 + e0 + 2) = t4[i][1];
    }

    if (tx == 0) {
#pragma unroll
        for (int i = 0; i < 2; i++) {
            float s1 = 0.f, s2v = 0.f, s3 = 0.f, s4 = 0.f;
            for (int dd = 0; dd < 64; dd++) {
                float u_r = Ur[r0 + i][dd], u_i = Ui[r0 + i][dd];
                float bm = bm_s[dd], bp = bp_s[dd];
                s1 += bm * u_r;  s2v += bp * u_i;
                s3 += bm * u_i;  s4 += bp * u_r;
            }
            int pt = pt0 + r0 + i;
            g_S4[pt][h][0] = s1;  g_S4[pt][h][1] = s2v;
            g_S4[pt][h][2] = s3;  g_S4[pt][h][3] = s4;
        }
    }
}

// ---------------- kernel 4: BD (hot loop) -> writes g_S2 ----------------
__global__ __launch_bounds__(256) void k_bd(
    const float* __restrict__ emb_r, const float* __restrict__ emb_i)
{
    int pt = blockIdx.x;
    int b  = pt % B_;
    int q  = (pt / B_) % Q_;
    int n  = pt / (B_ * Q_);

    __shared__ float4 T_s[32][16];
    __shared__ float  s_s[32];
    int t = threadIdx.x;
    const float4* Tg = &g_T[pt][0][0];
    for (int i = t; i < 32 * 16; i += 256) ((float4*)T_s)[i] = Tg[i];
    if (t < 32) s_s[t] = ((const float*)&g_S4[pt][0][0])[t];
    __syncthreads();

    int p  = t & 127;
    int hh = t >> 7;           // 0/1: handles h in [hh*4, hh*4+4)
    int h0 = hh * 4;

    const float4* rRR = (const float4*)(emb_r + ((((size_t)n * Q_ + q) * P_ + p) * B_ + b) * D_);
    const float4* rIR = (const float4*)(emb_i + ((((size_t)n * Q_ + q) * P_ + p) * B_ + b) * D_);
    const float4* rRC = (const float4*)(emb_r + ((((size_t)n * Q_ + p) * P_ + q) * B_ + b) * D_);
    const float4* rIC = (const float4*)(emb_i + ((((size_t)n * Q_ + p) * P_ + q) * B_ + b) * D_);

    float2 bdrP[4][2], bdrM[4][2], bdiP[4][2], bdiM[4][2];
#pragma unroll
    for (int hl = 0; hl < 4; hl++)
#pragma unroll
        for (int j = 0; j < 2; j++) {
            bdrP[hl][j] = make_float2(0.f, 0.f); bdrM[hl][j] = make_float2(0.f, 0.f);
            bdiP[hl][j] = make_float2(0.f, 0.f); bdiM[hl][j] = make_float2(0.f, 0.f);
        }

#pragma unroll 2
    for (int d4 = 0; d4 < 16; d4++) {
        float4 er = __ldg(rRR + d4);
        float4 ei = __ldg(rIR + d4);
        float4 fr = __ldg(rRC + d4);
        float4 fi = __ldg(rIC + d4);
        float2 er_a = make_float2(er.x, er.y), er_b = make_float2(er.z, er.w);
        float2 ei_a = make_float2(ei.x, ei.y), ei_b = make_float2(ei.z, ei.w);
        float2 fr_a = make_float2(fr.x, fr.y), fr_b = make_float2(fr.z, fr.w);
        float2 fi_a = make_float2(fi.x, fi.y), fi_b = make_float2(fi.z, fi.w);
#pragma unroll
        for (int hl = 0; hl < 4; hl++) {
            int hv = h0 + hl;
            float4 T1 = T_s[4 * hv + 0][d4];
            float4 T2 = T_s[4 * hv + 1][d4];
            float4 T3 = T_s[4 * hv + 2][d4];
            float4 T4 = T_s[4 * hv + 3][d4];
            float2 T1a = make_float2(T1.x, T1.y), T1b = make_float2(T1.z, T1.w);
            float2 T2a = make_float2(T2.x, T2.y), T2b = make_float2(T2.z, T2.w);
            float2 T3a = make_float2(T3.x, T3.y), T3b = make_float2(T3.z, T3.w);
            float2 T4a = make_float2(T4.x, T4.y), T4b = make_float2(T4.z, T4.w);
            fma2(bdrP[hl][0], er_a, T1a);  fma2(bdrP[hl][1], er_b, T1b);
            fma2(bdrM[hl][0], ei_a, T2a);  fma2(bdrM[hl][1], ei_b, T2b);
            fma2(bdrM[hl][0], fr_a, T4a);  fma2(bdrM[hl][1], fr_b, T4b);
            fma2(bdrM[hl][0], fi_a, T3a);  fma2(bdrM[hl][1], fi_b, T3b);
            fma2(bdiP[hl][0], er_a, T3a);  fma2(bdiP[hl][1], er_b, T3b);
            fma2(bdiP[hl][0], fr_a, T2a);  fma2(bdiP[hl][1], fr_b, T2b);
            fma2(bdiP[hl][0], fi_a, T1a);  fma2(bdiP[hl][1], fi_b, T1b);
            fma2(bdiM[hl][0], ei_a, T4a);  fma2(bdiM[hl][1], ei_b, T4b);
        }
    }

#pragma unroll
    for (int hl = 0; hl < 4; hl++) {
        int hv = h0 + hl;
        float rp = (bdrP[hl][0].x + bdrP[hl][0].y) + (bdrP[hl][1].x + bdrP[hl][1].y);
        float rm = (bdrM[hl][0].x + bdrM[hl][0].y) + (bdrM[hl][1].x + bdrM[hl][1].y);
        float ip = (bdiP[hl][0].x + bdiP[hl][0].y) + (bdiP[hl][1].x + bdiP[hl][1].y);
        float im = (bdiM[hl][0].x + bdiM[hl][0].y) + (bdiM[hl][1].x + bdiM[hl][1].y);
        float r  = rp - rm + s_s[hv * 4 + 0] - s_s[hv * 4 + 1];
        float iv = ip - im + s_s[hv * 4 + 2] + s_s[hv * 4 + 3];
        g_S2[hv][n][q][b][p] = sqrtf(r * r + iv * iv);
    }
}

// ---------------- kernel 5: AC magnitudes, interleaved-k complex GEMM ----------------
// grid (8 = qt(4)*pt(2), B, H*N), block 256: tx(32)->p, ty(8)->4q. Norm folded.
__global__ __launch_bounds__(256) void k_ac(
    const float* __restrict__ ww_r_g, const float* __restrict__ ww_r_bt,
    const float* __restrict__ ww_i_g, const float* __restrict__ ww_i_bt)
{
    int b = blockIdx.y;
    int h = blockIdx.z / N_, n = blockIdx.z % N_;
    int pt = blockIdx.x & 1, qt = blockIdx.x >> 1;
    int q0 = qt * 32, p0 = pt * 64;

    __shared__ float2 kT[64][65];                // [d][p] interleaved (kr,ki)
    __shared__ float  qrT[64][34], qiT[64][34];  // [d][q]
    __shared__ float  Akr[64], Ckr[64], Aki[64], Cki[64];
    __shared__ float  Aqr[64], Cqr[64], Aqi[64], Cqi[64];

    int t = threadIdx.x;
    if (t < 64) {
        int d = t;
        float m0 = g_mean[0][h][n][d], r0s = g_rstd[0][h][n][d];
        float m1 = g_mean[1][h][n][d], r1s = g_rstd[1][h][n][d];
        Akr[d] = r0s;  Ckr[d] = -m0 * r0s;
        Aki[d] = r1s;  Cki[d] = -m1 * r1s;
        float m2 = g_mean[2][h][n][d], r2s = g_rstd[2][h][n][d];
        float m3 = g_mean[3][h][n][d], r3s = g_rstd[3][h][n][d];
        float gr = ww_r_g[h * 64 + d], btr = ww_r_bt[h * 64 + d];
        float gi = ww_i_g[h * 64 + d], bti = ww_i_bt[h * 64 + d];
        Aqr[d] = r2s * gr;  Cqr[d] = btr - m2 * r2s * gr;
        Aqi[d] = r3s * gi;  Cqi[d] = bti - m3 * r3s * gi;
    }
    __syncthreads();

    for (int i = t; i < 64 * 64; i += 256) {
        int p = i >> 6, d = i & 63;
        int row = (n * P_ + p0 + p) * B_ + b;
        float xr = g_wk_r[h][row][d];
        float xi = g_wk_i[h][row][d];
        kT[d][p] = make_float2(xr * Akr[d] + Ckr[d], xi * Aki[d] + Cki[d]);
    }
    for (int i = t; i < 32 * 64; i += 256) {
        int q = i >> 6, d = i & 63;
        int row = (n * Q_ + q0 + q) * B_ + b;
        qrT[d][q] = g_wq_r[h][row][d] * Aqr[d] + Cqr[d];
        qiT[d][q] = g_wq_i[h][row][d] * Aqi[d] + Cqi[d];
    }
    __syncthreads();

    int tx = t & 31, ty = t >> 5;
    int lq0 = ty * 4;

    float2 accR[2][2], accI[2][2];   // [q-pair ii][p j], p_j = tx + 32*j
#pragma unroll
    for (int ii = 0; ii < 2; ii++)
#pragma unroll
        for (int j = 0; j < 2; j++) { accR[ii][j] = make_float2(0.f, 0.f); accI[ii][j] = make_float2(0.f, 0.f); }

#pragma unroll 4
    for (int d = 0; d < 64; d++) {
        float2 kv0 = kT[d][tx];
        float2 kv1 = kT[d][tx + 32];
        float2 qr20 = *(const float2*)&qrT[d][lq0];
        float2 qr21 = *(const float2*)&qrT[d][lq0 + 2];
        float2 qi20 = *(const float2*)&qiT[d][lq0];
        float2 qi21 = *(const float2*)&qiT[d][lq0 + 2];
        float2 nqi20 = neg2(qi20), nqi21 = neg2(qi21);
        {
            float2 kr2 = dup2(kv0.x), ki2 = dup2(kv0.y);
            fma2(accR[0][0], qr20, kr2);  fma2(accR[0][0], nqi20, ki2);
            fma2(accI[0][0], qr20, ki2);  fma2(accI[0][0], qi20,  kr2);
            fma2(accR[1][0], qr21, kr2);  fma2(accR[1][0], nqi21, ki2);
            fma2(accI[1][0], qr21, ki2);  fma2(accI[1][0], qi21,  kr2);
        }
        {
            float2 kr2 = dup2(kv1.x), ki2 = dup2(kv1.y);
            fma2(accR[0][1], qr20, kr2);  fma2(accR[0][1], nqi20, ki2);
            fma2(accI[0][1], qr20, ki2);  fma2(accI[0][1], qi20,  kr2);
            fma2(accR[1][1], qr21, kr2);  fma2(accR[1][1], nqi21, ki2);
            fma2(accI[1][1], qr21, ki2);  fma2(accI[1][1], qi21,  kr2);
        }
    }

#pragma unroll
    for (int ii = 0; ii < 2; ii++)
#pragma unroll
        for (int j = 0; j < 2; j++) {
            int qg = q0 + lq0 + 2 * ii;
            int p  = p0 + tx + 32 * j;
            float r0v = accR[ii][j].x, i0v = accI[ii][j].x;
            float r1v = accR[ii][j].y, i1v = accI[ii][j].y;
            g_S[h][n][qg][b][p]     = sqrtf(r0v * r0v + i0v * i0v);
            g_S[h][n][qg + 1][b][p] = sqrtf(r1v * r1v + i1v * i1v);
        }
}

// ---------------- kernel 6: softmax over b (sums AC + BD) ----------------
__global__ __launch_bounds__(256) void k_softmax()
{
    int idx = blockIdx.x * 256 + threadIdx.x;
    int p  = idx % P_;
    int q  = (idx / P_) % Q_;
    int hn = idx / (P_ * Q_);
    size_t off = (((size_t)hn * Q_ + q) * B_) * P_ + p;
    float* baseA = &g_S[0][0][0][0][0] + off;
    const float* baseB = &g_S2[0][0][0][0][0] + off;
    float v0 = (baseA[0 * P_] + baseB[0 * P_]) * TEMPF;
    float v1 = (baseA[1 * P_] + baseB[1 * P_]) * TEMPF;
    float v2 = (baseA[2 * P_] + baseB[2 * P_]) * TEMPF;
    float v3 = (baseA[3 * P_] + baseB[3 * P_]) * TEMPF;
    float m = fmaxf(fmaxf(v0, v1), fmaxf(v2, v3));
    v0 = __expf(v0 - m); v1 = __expf(v1 - m); v2 = __expf(v2 - m); v3 = __expf(v3 - m);
    float inv = 1.f / (v0 + v1 + v2 + v3);
    baseA[0 * P_] = v0 * inv;
    baseA[1 * P_] = v1 * inv;
    baseA[2 * P_] = v2 * inv;
    baseA[3 * P_] = v3 * inv;
}

// ---------------- kernel 7: output aggregation (GEMM per (h,n,b,q-tile)) ----------------
// grid (4 q-tiles of 32, B, H*N), block 256: tx(16)->4d, ty(16)->2q
__global__ __launch_bounds__(256) void k_out(
    const float* __restrict__ vr, const float* __restrict__ vi,
    float* __restrict__ out)
{
    int b = blockIdx.y;
    int h = blockIdx.z / N_, n = blockIdx.z % N_;
    int q0 = blockIdx.x * 32;

    __shared__ float aff_s[32][64];          // [q][p-chunk]
    __shared__ float vr_s[64][D_], vi_s[64][D_];

    int t = threadIdx.x;
    int tx = t & 15, ty = t >> 4;
    int d0 = tx * 4, lq0 = ty * 2;

    float2 cr[2][2], ci[2][2];
#pragma unroll
    for (int i = 0; i < 2; i++)
#pragma unroll
        for (int j = 0; j < 2; j++) { cr[i][j] = make_float2(0.f, 0.f); ci[i][j] = make_float2(0.f, 0.f); }

    for (int c = 0; c < 2; c++) {
        __syncthreads();
        int p0 = c * 64;
        for (int i = t; i < 32 * 64; i += 256) {
            int lq = i >> 6, pp = i & 63;
            aff_s[lq][pp] = g_S[h][n][q0 + lq][b][p0 + pp];
        }
        for (int i = t; i < 64 * D_; i += 256) {
            int pp = i >> 6, d = i & 63;
            size_t off = (((size_t)n * P_ + p0 + pp) * B_ + b) * D_ + d;
            vr_s[pp][d] = vr[off];
            vi_s[pp][d] = vi[off];
        }
        __syncthreads();

#pragma unroll 4
        for (int pp = 0; pp < 64; pp++) {
            float2 v_r0 = *(const float2*)&vr_s[pp][d0];
            float2 v_r1 = *(const float2*)&vr_s[pp][d0 + 2];
            float2 v_i0 = *(const float2*)&vi_s[pp][d0];
            float2 v_i1 = *(const float2*)&vi_s[pp][d0 + 2];
#pragma unroll
            for (int i = 0; i < 2; i++) {
                float2 a2 = dup2(aff_s[lq0 + i][pp]);
                fma2(cr[i][0], a2, v_r0);  fma2(cr[i][1], a2, v_r1);
                fma2(ci[i][0], a2, v_i0);  fma2(ci[i][1], a2, v_i1);
            }
        }
    }

#pragma unroll
    for (int i = 0; i < 2; i++) {
        int qg = q0 + lq0 + i;
        size_t o = (((size_t)n * Q_ + qg) * B_ + b) * (H_ * D_) + h * D_ + d0;
        *(float2*)(out + o)     = cr[i][0];
        *(float2*)(out + o + 2) = cr[i][1];
        size_t oi = o + (size_t)N_ * Q_ * B_ * H_ * D_;
        *(float2*)(out + oi)     = ci[i][0];
        *(float2*)(out + oi + 2) = ci[i][1];
    }
}

// ---------------- launch ----------------
extern "C" void kernel_launch(void* const* d_in, const int* in_sizes, int n_in,
                              void* d_out, int out_size)
{
    const float* query_r = (const float*)d_in[0];
    const float* query_i = (const float*)d_in[1];
    const float* key_r   = (const float*)d_in[2];
    const float* key_i   = (const float*)d_in[3];
    const float* val_r   = (const float*)d_in[4];
    const float* val_i   = (const float*)d_in[5];
    const float* emb_r   = (const float*)d_in[6];
    const float* emb_i   = (const float*)d_in[7];
    const float* WKr_w   = (const float*)d_in[8];
    const float* WKr_b   = (const float*)d_in[9];
    const float* WKi_w   = (const float*)d_in[10];
    const float* WKi_b   = (const float*)d_in[11];
    const float* WKRr_w  = (const float*)d_in[12];
    const float* WKRr_b  = (const float*)d_in[13];
    const float* WKRi_w  = (const float*)d_in[14];
    const float* WKRi_b  = (const float*)d_in[15];
    const float* WQr_w   = (const float*)d_in[16];
    const float* WQr_b   = (const float*)d_in[17];
    const float* WQi_w   = (const float*)d_in[18];
    const float* WQi_b   = (const float*)d_in[19];
    const float* ww_r_g  = (const float*)d_in[20];
    const float* ww_r_bt = (const float*)d_in[21];
    const float* ww_i_g  = (const float*)d_in[22];
    const float* ww_i_bt = (const float*)d_in[23];
    const float* wr_r_g  = (const float*)d_in[24];
    const float* wr_r_bt = (const float*)d_in[25];
    const float* wr_i_g  = (const float*)d_in[26];
    const float* wr_i_bt = (const float*)d_in[27];

    k_proj<<<dim3(32, H_, 2), 256>>>(key_r, key_i, query_r, query_i,
                                     WKr_w, WKr_b, WKi_w, WKi_b,
                                     WQr_w, WQr_b, WQi_w, WQi_b);
    k_stats<<<dim3(N_, H_, 4), 512>>>();
    k_tvec<<<dim3(32, H_), 256>>>(WKRr_w, WKRr_b, WKRi_w, WKRi_b,
                                  wr_r_g, wr_r_bt, wr_i_g, wr_i_bt);
    k_bd<<<ROWS_, 256>>>(emb_r, emb_i);
    k_ac<<<dim3(8, B_, H_ * N_), 256>>>(ww_r_g, ww_r_bt, ww_i_g, ww_i_bt);
    k_softmax<<<1024, 256>>>();
    k_out<<<dim3(4, B_, H_ * N_), 256>>>(val_r, val_i, (float*)d_out);
}

// round 6
// speedup vs baseline: 1.7863x; 1.3003x over previous
#include <cuda_runtime.h>
#include <math.h>

#define H_ 8
#define D_ 64
#define N_ 2
#define Q_ 128
#define P_ 128
#define B_ 4
#define ROWS_ 1024          // N_*Q_*B_ == N_*P_*B_
#define EPSF 1e-5f
#define TEMPF 30.0f

// dynamic smem bytes for k_bd: 4 arrays [64][17] float4 + T [32][16] float4 + 32 floats
#define SMEM_BD ((4 * 64 * 17 + 32 * 16) * 16 + 128)

// ---------------- packed fp32x2 FMA (sm_103a FFMA2) ----------------
__device__ __forceinline__ void fma2(float2& d, float2 a, float2 b) {
    asm("fma.rn.f32x2 %0, %1, %2, %0;"
        : "+l"(reinterpret_cast<unsigned long long&>(d))
        : "l"(reinterpret_cast<unsigned long long&>(a)),
          "l"(reinterpret_cast<unsigned long long&>(b)));
}
__device__ __forceinline__ float2 dup2(float v) { return make_float2(v, v); }
__device__ __forceinline__ float2 neg2(float2 v) { return make_float2(-v.x, -v.y); }

// ---------------- scratch (device globals; no allocation) ----------------
__device__ float  g_wk_r[H_][ROWS_][D_];   // RAW projections (pre-norm)
__device__ float  g_wk_i[H_][ROWS_][D_];
__device__ float  g_wq_r[H_][ROWS_][D_];
__device__ float  g_wq_i[H_][ROWS_][D_];
__device__ float  g_mean[4][H_][N_][64];   // a: 0 wk_r, 1 wk_i, 2 wq_r, 3 wq_i
__device__ float  g_rstd[4][H_][N_][64];
__device__ float4 g_T [ROWS_][32][16];     // per (n,q,b): 32 t-vectors of 64 floats
__device__ float  g_S4[ROWS_][H_][4];      // bias scalars s1..s4
__device__ float  g_S [H_][N_][Q_][B_][P_];// AC scores -> aff
__device__ float  g_S2[H_][N_][Q_][B_][P_];// BD magnitudes

// ---------------- kernel 1: complex projections, register-tiled ----------------
// grid (32 row-tiles of 32, H, 2{key,query}), block 256 = 16x16, thread 2row x 4d
__global__ __launch_bounds__(256) void k_proj(
    const float* __restrict__ kr, const float* __restrict__ ki,
    const float* __restrict__ qr, const float* __restrict__ qi,
    const float* __restrict__ WKr, const float* __restrict__ WKrb,
    const float* __restrict__ WKi, const float* __restrict__ WKib,
    const float* __restrict__ WQr, const float* __restrict__ WQrb,
    const float* __restrict__ WQi, const float* __restrict__ WQib)
{
    int h   = blockIdx.y;
    int isQ = blockIdx.z;
    const float* xr = isQ ? qr : kr;
    const float* xi = isQ ? qi : ki;
    const float* Wr = (isQ ? WQr : WKr) + h * D_ * D_;
    const float* Wi = (isQ ? WQi : WKi) + h * D_ * D_;
    const float* br = (isQ ? WQrb : WKrb) + h * D_;
    const float* bi = (isQ ? WQib : WKib) + h * D_;
    float* outR = isQ ? &g_wq_r[h][0][0] : &g_wk_r[h][0][0];
    float* outI = isQ ? &g_wq_i[h][0][0] : &g_wk_i[h][0][0];

    __shared__ float Wr_t[D_][66];   // [e][d]
    __shared__ float Wi_t[D_][66];
    __shared__ float Xr[32][D_], Xi[32][D_];

    int t = threadIdx.x;
    for (int i = t; i < D_ * D_; i += 256) {
        int d = i >> 6, e = i & 63;
        Wr_t[e][d] = Wr[i];
        Wi_t[e][d] = Wi[i];
    }
    int row0 = blockIdx.x * 32;
    const float4* xr4 = (const float4*)(xr + (size_t)row0 * D_);
    const float4* xi4 = (const float4*)(xi + (size_t)row0 * D_);
    for (int i = t; i < 32 * D_ / 4; i += 256) {
        ((float4*)Xr)[i] = xr4[i];
        ((float4*)Xi)[i] = xi4[i];
    }
    __syncthreads();

    int tx = t & 15, ty = t >> 4;
    int d0 = tx * 4, r0 = ty * 2;

    float2 ar[2][2], ai[2][2];
#pragma unroll
    for (int i = 0; i < 2; i++)
#pragma unroll
        for (int j = 0; j < 2; j++) { ar[i][j] = make_float2(0.f, 0.f); ai[i][j] = make_float2(0.f, 0.f); }

#pragma unroll 4
    for (int e = 0; e < 64; e++) {
        float2 wr0 = *(const float2*)&Wr_t[e][d0];
        float2 wr1 = *(const float2*)&Wr_t[e][d0 + 2];
        float2 wi0 = *(const float2*)&Wi_t[e][d0];
        float2 wi1 = *(const float2*)&Wi_t[e][d0 + 2];
        float2 nwi0 = neg2(wi0), nwi1 = neg2(wi1);
#pragma unroll
        for (int i = 0; i < 2; i++) {
            float2 v2r = dup2(Xr[r0 + i][e]);
            float2 v2i = dup2(Xi[r0 + i][e]);
            fma2(ar[i][0], v2r, wr0);  fma2(ar[i][0], v2i, nwi0);
            fma2(ar[i][1], v2r, wr1);  fma2(ar[i][1], v2i, nwi1);
            fma2(ai[i][0], v2r, wi0);  fma2(ai[i][0], v2i, wr0);
            fma2(ai[i][1], v2r, wi1);  fma2(ai[i][1], v2i, wr1);
        }
    }

    float2 bR0 = *(const float2*)&br[d0];
    float2 bR1 = *(const float2*)&br[d0 + 2];
    float2 bI0 = *(const float2*)&bi[d0];
    float2 bI1 = *(const float2*)&bi[d0 + 2];
#pragma unroll
    for (int i = 0; i < 2; i++) {
        ar[i][0].x += bR0.x - bI0.x;  ar[i][0].y += bR0.y - bI0.y;
        ar[i][1].x += bR1.x - bI1.x;  ar[i][1].y += bR1.y - bI1.y;
        ai[i][0].x += bR0.x + bI0.x;  ai[i][0].y += bR0.y + bI0.y;
        ai[i][1].x += bR1.x + bI1.x;  ai[i][1].y += bR1.y + bI1.y;
        float2* oR = (float2*)(outR + (size_t)(row0 + r0 + i) * D_ + d0);
        float2* oI = (float2*)(outI + (size_t)(row0 + r0 + i) * D_ + d0);
        oR[0] = ar[i][0];  oR[1] = ar[i][1];
        oI[0] = ai[i][0];  oI[1] = ai[i][1];
    }
}

// ---------------- kernel 2: instance-norm STATS only (no normalize pass) ----------------
// grid (N_, H_, 4), block 512
__global__ __launch_bounds__(512) void k_stats()
{
    int n = blockIdx.x, h = blockIdx.y, a = blockIdx.z;
    const float* base;
    if      (a == 0) base = &g_wk_r[0][0][0];
    else if (a == 1) base = &g_wk_i[0][0][0];
    else if (a == 2) base = &g_wq_r[0][0][0];
    else             base = &g_wq_i[0][0][0];
    const float* x = base + ((size_t)h * ROWS_ + (size_t)n * 512) * D_;

    int t = threadIdx.x;
    int d = t & 63, c = t >> 6;       // 8 chunks of 64 rows
    float s = 0.f, s2 = 0.f;
    for (int r = c * 64; r < (c + 1) * 64; r++) {
        float v = x[r * 64 + d];
        s += v; s2 += v * v;
    }
    __shared__ float Ss[8][64], S2s[8][64];
    Ss[c][d] = s; S2s[c][d] = s2;
    __syncthreads();
    if (t < 64) {
        float sum = 0.f, sum2 = 0.f;
#pragma unroll
        for (int cc = 0; cc < 8; cc++) { sum += Ss[cc][t]; sum2 += S2s[cc][t]; }
        float m   = sum * (1.f / 512.f);
        float var = sum2 * (1.f / 512.f) - m * m;
        g_mean[a][h][n][t] = m;
        g_rstd[a][h][n][t] = rsqrtf(var + EPSF);
    }
}

// ---------------- kernel 3: t-vectors (GEMM) + bias scalars (norm folded) ----------------
// grid (32 row-tiles of 32, H), block 256 = 16x16
__global__ __launch_bounds__(256) void k_tvec(
    const float* __restrict__ WKRr, const float* __restrict__ WKRrb,
    const float* __restrict__ WKRi, const float* __restrict__ WKRib,
    const float* __restrict__ wr_r_g, const float* __restrict__ wr_r_bt,
    const float* __restrict__ wr_i_g, const float* __restrict__ wr_i_bt)
{
    int h = blockIdx.y;
    int pt0 = blockIdx.x * 32;
    int n = pt0 >> 9;                 // rows 0..511 -> n=0, 512.. -> n=1
    __shared__ float Ur[32][D_], Ui[32][D_];
    __shared__ float Wr_s[64][66], Wi_s[64][66];   // [d][e]
    __shared__ float bm_s[64], bp_s[64];
    __shared__ float Ar_s[64], Cr_s[64], Ai_s[64], Ci_s[64];

    int t = threadIdx.x;
    const float* Wr = WKRr + h * D_ * D_;
    const float* Wi = WKRi + h * D_ * D_;
    for (int i = t; i < D_ * D_; i += 256) {
        int dd = i >> 6, e = i & 63;
        Wr_s[dd][e] = Wr[i];
        Wi_s[dd][e] = Wi[i];
    }
    if (t < 64) {
        float brv = WKRrb[h * D_ + t], biv = WKRib[h * D_ + t];
        bm_s[t] = brv - biv;
        bp_s[t] = brv + biv;
        // wr-affine folded with instance-norm of raw wq
        float m2 = g_mean[2][h][n][t], r2 = g_rstd[2][h][n][t];
        float m3 = g_mean[3][h][n][t], r3 = g_rstd[3][h][n][t];
        float gr = wr_r_g[h * 64 + t], btr = wr_r_bt[h * 64 + t];
        float gi = wr_i_g[h * 64 + t], bti = wr_i_bt[h * 64 + t];
        Ar_s[t] = r2 * gr;  Cr_s[t] = btr - m2 * r2 * gr;
        Ai_s[t] = r3 * gi;  Ci_s[t] = bti - m3 * r3 * gi;
    }
    __syncthreads();
    for (int i = t; i < 32 * D_; i += 256) {
        int l = i >> 6, d = i & 63;
        Ur[l][d] = g_wq_r[h][pt0 + l][d] * Ar_s[d] + Cr_s[d];
        Ui[l][d] = g_wq_i[h][pt0 + l][d] * Ai_s[d] + Ci_s[d];
    }
    __syncthreads();

    int tx = t & 15, ty = t >> 4;
    int e0 = tx * 4, r0 = ty * 2;

    float2 t1[2][2], t2[2][2], t3[2][2], t4[2][2];
#pragma unroll
    for (int i = 0; i < 2; i++)
#pragma unroll
        for (int j = 0; j < 2; j++) {
            t1[i][j] = make_float2(0.f, 0.f); t2[i][j] = make_float2(0.f, 0.f);
            t3[i][j] = make_float2(0.f, 0.f); t4[i][j] = make_float2(0.f, 0.f);
        }

#pragma unroll 4
    for (int dd = 0; dd < 64; dd++) {
        float2 wr0 = *(const float2*)&Wr_s[dd][e0];
        float2 wr1 = *(const float2*)&Wr_s[dd][e0 + 2];
        float2 wi0 = *(const float2*)&Wi_s[dd][e0];
        float2 wi1 = *(const float2*)&Wi_s[dd][e0 + 2];
#pragma unroll
        for (int i = 0; i < 2; i++) {
            float2 u2r = dup2(Ur[r0 + i][dd]);
            float2 u2i = dup2(Ui[r0 + i][dd]);
            fma2(t1[i][0], u2r, wr0);  fma2(t1[i][1], u2r, wr1);
            fma2(t2[i][0], u2r, wi0);  fma2(t2[i][1], u2r, wi1);
            fma2(t3[i][0], u2i, wr0);  fma2(t3[i][1], u2i, wr1);
            fma2(t4[i][0], u2i, wi0);  fma2(t4[i][1], u2i, wi1);
        }
    }

#pragma unroll
    for (int i = 0; i < 2; i++) {
        float* base = (float*)&g_T[pt0 + r0 + i][h * 4][0];   // 4 vecs x 64 floats
        *(float2*)(base +   0 + e0) = t1[i][0];  *(float2*)(base +   0 + e0 + 2) = t1[i][1];
        *(float2*)(base +  64 + e0) = t2[i][0];  *(float2*)(base +  64 + e0 + 2) = t2[i][1];
        *(float2*)(base + 128 + e0) = t3[i][0];  *(float2*)(base + 128 + e0 + 2) = t3[i][1];
        *(float2*)(base + 192 + e0) = t4[i][0];  *(float2*)(base + 192 + e0 + 2) = t4[i][1];
    }

    if (tx == 0) {
#pragma unroll
        for (int i = 0; i < 2; i++) {
            float s1 = 0.f, s2v = 0.f, s3 = 0.f, s4 = 0.f;
            for (int dd = 0; dd < 64; dd++) {
                float u_r = Ur[r0 + i][dd], u_i = Ui[r0 + i][dd];
                float bm = bm_s[dd], bp = bp_s[dd];
                s1 += bm * u_r;  s2v += bp * u_i;
                s3 += bm * u_i;  s4 += bp * u_r;
            }
            int pt = pt0 + r0 + i;
            g_S4[pt][h][0] = s1;  g_S4[pt][h][1] = s2v;
            g_S4[pt][h][2] = s3;  g_S4[pt][h][3] = s4;
        }
    }
}

// ---------------- kernel 4: BD (hot loop) — smem-staged both orientations ----------------
// grid 1024 points (n,q,b), block 256. Two 64-p stages; dynamic smem (SMEM_BD).
// Compute threads: p(64) x hgroup(4), 2 heads per thread.
__global__ __launch_bounds__(256) void k_bd(
    const float4* __restrict__ emb_r4, const float4* __restrict__ emb_i4)
{
    int pt = blockIdx.x;
    int b  = pt & 3;
    int q  = (pt >> 2) & 127;
    int n  = pt >> 9;

    extern __shared__ float4 smem4[];
    float4* Er_s = smem4;                 // [64][17]
    float4* Ei_s = Er_s + 64 * 17;
    float4* Fr_s = Ei_s + 64 * 17;
    float4* Fi_s = Fr_s + 64 * 17;
    float4* T_s  = Fi_s + 64 * 17;        // [32][16]
    float*  s_s  = (float*)(T_s + 32 * 16);

    int t = threadIdx.x;
    const float4* Tg = &g_T[pt][0][0];
    for (int i = t; i < 512; i += 256) T_s[i] = Tg[i];
    if (t < 32) s_s[t] = ((const float*)&g_S4[pt][0][0])[t];

    int p  = t & 63;
    int hg = t >> 6;            // 0..3
    int h0 = hg * 2;

    // base offsets in float4 units
    long baseE = (((long)n * 128 + q) * 128) * 4 + b;   // + x*4 rows, then *16
    long baseF = (((long)n * 128) * 128 + q) * 4 + b;   // + x*512 rows

#pragma unroll 1
    for (int stage = 0; stage < 2; stage++) {
        int p0 = stage * 64;
        __syncthreads();     // smem (incl. T on stage 0) safe to (re)fill / fully loaded
#pragma unroll
        for (int k = 0; k < 4; k++) {
            int i  = t + k * 256;
            int pl = i >> 4, d4 = i & 15;
            long eIdx = (baseE + (long)(p0 + pl) * 4) * 16 + d4;
            long fIdx = (baseF + (long)(p0 + pl) * 512) * 16 + d4;
            Er_s[pl * 17 + d4] = __ldg(emb_r4 + eIdx);
            Ei_s[pl * 17 + d4] = __ldg(emb_i4 + eIdx);
            Fr_s[pl * 17 + d4] = __ldg(emb_r4 + fIdx);
            Fi_s[pl * 17 + d4] = __ldg(emb_i4 + fIdx);
        }
        __syncthreads();

        float2 bdrP[2][2], bdrM[2][2], bdiP[2][2], bdiM[2][2];
#pragma unroll
        for (int hl = 0; hl < 2; hl++)
#pragma unroll
            for (int j = 0; j < 2; j++) {
                bdrP[hl][j] = make_float2(0.f, 0.f); bdrM[hl][j] = make_float2(0.f, 0.f);
                bdiP[hl][j] = make_float2(0.f, 0.f); bdiM[hl][j] = make_float2(0.f, 0.f);
            }

#pragma unroll 4
        for (int d4 = 0; d4 < 16; d4++) {
            float4 er = Er_s[p * 17 + d4];
            float4 ei = Ei_s[p * 17 + d4];
            float4 fr = Fr_s[p * 17 + d4];
            float4 fi = Fi_s[p * 17 + d4];
            float2 er_a = make_float2(er.x, er.y), er_b = make_float2(er.z, er.w);
            float2 ei_a = make_float2(ei.x, ei.y), ei_b = make_float2(ei.z, ei.w);
            float2 fr_a = make_float2(fr.x, fr.y), fr_b = make_float2(fr.z, fr.w);
            float2 fi_a = make_float2(fi.x, fi.y), fi_b = make_float2(fi.z, fi.w);
#pragma unroll
            for (int hl = 0; hl < 2; hl++) {
                int hv = h0 + hl;
                float4 T1 = T_s[(4 * hv + 0) * 16 + d4];
                float4 T2 = T_s[(4 * hv + 1) * 16 + d4];
                float4 T3 = T_s[(4 * hv + 2) * 16 + d4];
                float4 T4 = T_s[(4 * hv + 3) * 16 + d4];
                float2 T1a = make_float2(T1.x, T1.y), T1b = make_float2(T1.z, T1.w);
                float2 T2a = make_float2(T2.x, T2.y), T2b = make_float2(T2.z, T2.w);
                float2 T3a = make_float2(T3.x, T3.y), T3b = make_float2(T3.z, T3.w);
                float2 T4a = make_float2(T4.x, T4.y), T4b = make_float2(T4.z, T4.w);
                fma2(bdrP[hl][0], er_a, T1a);  fma2(bdrP[hl][1], er_b, T1b);
                fma2(bdrM[hl][0], ei_a, T2a);  fma2(bdrM[hl][1], ei_b, T2b);
                fma2(bdrM[hl][0], fr_a, T4a);  fma2(bdrM[hl][1], fr_b, T4b);
                fma2(bdrM[hl][0], fi_a, T3a);  fma2(bdrM[hl][1], fi_b, T3b);
                fma2(bdiP[hl][0], er_a, T3a);  fma2(bdiP[hl][1], er_b, T3b);
                fma2(bdiP[hl][0], fr_a, T2a);  fma2(bdiP[hl][1], fr_b, T2b);
                fma2(bdiP[hl][0], fi_a, T1a);  fma2(bdiP[hl][1], fi_b, T1b);
                fma2(bdiM[hl][0], ei_a, T4a);  fma2(bdiM[hl][1], ei_b, T4b);
            }
        }

#pragma unroll
        for (int hl = 0; hl < 2; hl++) {
            int hv = h0 + hl;
            float rp = (bdrP[hl][0].x + bdrP[hl][0].y) + (bdrP[hl][1].x + bdrP[hl][1].y);
            float rm = (bdrM[hl][0].x + bdrM[hl][0].y) + (bdrM[hl][1].x + bdrM[hl][1].y);
            float ip = (bdiP[hl][0].x + bdiP[hl][0].y) + (bdiP[hl][1].x + bdiP[hl][1].y);
            float im = (bdiM[hl][0].x + bdiM[hl][0].y) + (bdiM[hl][1].x + bdiM[hl][1].y);
            float r  = rp - rm + s_s[hv * 4 + 0] - s_s[hv * 4 + 1];
            float iv = ip - im + s_s[hv * 4 + 2] + s_s[hv * 4 + 3];
            g_S2[hv][n][q][b][p0 + p] = sqrtf(r * r + iv * iv);
        }
    }
}

// ---------------- kernel 5: AC magnitudes, interleaved-k complex GEMM ----------------
// grid (8 = qt(4)*pt(2), B, H*N), block 256: tx(32)->p, ty(8)->4q. Norm folded.
__global__ __launch_bounds__(256) void k_ac(
    const float* __restrict__ ww_r_g, const float* __restrict__ ww_r_bt,
    const float* __restrict__ ww_i_g, const float* __restrict__ ww_i_bt)
{
    int b = blockIdx.y;
    int h = blockIdx.z / N_, n = blockIdx.z % N_;
    int pt = blockIdx.x & 1, qt = blockIdx.x >> 1;
    int q0 = qt * 32, p0 = pt * 64;

    __shared__ float2 kT[64][65];                // [d][p] interleaved (kr,ki)
    __shared__ float  qrT[64][34], qiT[64][34];  // [d][q]
    __shared__ float  Akr[64], Ckr[64], Aki[64], Cki[64];
    __shared__ float  Aqr[64], Cqr[64], Aqi[64], Cqi[64];

    int t = threadIdx.x;
    if (t < 64) {
        int d = t;
        float m0 = g_mean[0][h][n][d], r0s = g_rstd[0][h][n][d];
        float m1 = g_mean[1][h][n][d], r1s = g_rstd[1][h][n][d];
        Akr[d] = r0s;  Ckr[d] = -m0 * r0s;
        Aki[d] = r1s;  Cki[d] = -m1 * r1s;
        float m2 = g_mean[2][h][n][d], r2s = g_rstd[2][h][n][d];
        float m3 = g_mean[3][h][n][d], r3s = g_rstd[3][h][n][d];
        float gr = ww_r_g[h * 64 + d], btr = ww_r_bt[h * 64 + d];
        float gi = ww_i_g[h * 64 + d], bti = ww_i_bt[h * 64 + d];
        Aqr[d] = r2s * gr;  Cqr[d] = btr - m2 * r2s * gr;
        Aqi[d] = r3s * gi;  Cqi[d] = bti - m3 * r3s * gi;
    }
    __syncthreads();

    for (int i = t; i < 64 * 64; i += 256) {
        int p = i >> 6, d = i & 63;
        int row = (n * P_ + p0 + p) * B_ + b;
        float xr = g_wk_r[h][row][d];
        float xi = g_wk_i[h][row][d];
        kT[d][p] = make_float2(xr * Akr[d] + Ckr[d], xi * Aki[d] + Cki[d]);
    }
    for (int i = t; i < 32 * 64; i += 256) {
        int q = i >> 6, d = i & 63;
        int row = (n * Q_ + q0 + q) * B_ + b;
        qrT[d][q] = g_wq_r[h][row][d] * Aqr[d] + Cqr[d];
        qiT[d][q] = g_wq_i[h][row][d] * Aqi[d] + Cqi[d];
    }
    __syncthreads();

    int tx = t & 31, ty = t >> 5;
    int lq0 = ty * 4;

    float2 accR[2][2], accI[2][2];   // [q-pair ii][p j], p_j = tx + 32*j
#pragma unroll
    for (int ii = 0; ii < 2; ii++)
#pragma unroll
        for (int j = 0; j < 2; j++) { accR[ii][j] = make_float2(0.f, 0.f); accI[ii][j] = make_float2(0.f, 0.f); }

#pragma unroll 4
    for (int d = 0; d < 64; d++) {
        float2 kv0 = kT[d][tx];
        float2 kv1 = kT[d][tx + 32];
        float2 qr20 = *(const float2*)&qrT[d][lq0];
        float2 qr21 = *(const float2*)&qrT[d][lq0 + 2];
        float2 qi20 = *(const float2*)&qiT[d][lq0];
        float2 qi21 = *(const float2*)&qiT[d][lq0 + 2];
        float2 nqi20 = neg2(qi20), nqi21 = neg2(qi21);
        {
            float2 kr2 = dup2(kv0.x), ki2 = dup2(kv0.y);
            fma2(accR[0][0], qr20, kr2);  fma2(accR[0][0], nqi20, ki2);
            fma2(accI[0][0], qr20, ki2);  fma2(accI[0][0], qi20,  kr2);
            fma2(accR[1][0], qr21, kr2);  fma2(accR[1][0], nqi21, ki2);
            fma2(accI[1][0], qr21, ki2);  fma2(accI[1][0], qi21,  kr2);
        }
        {
            float2 kr2 = dup2(kv1.x), ki2 = dup2(kv1.y);
            fma2(accR[0][1], qr20, kr2);  fma2(accR[0][1], nqi20, ki2);
            fma2(accI[0][1], qr20, ki2);  fma2(accI[0][1], qi20,  kr2);
            fma2(accR[1][1], qr21, kr2);  fma2(accR[1][1], nqi21, ki2);
            fma2(accI[1][1], qr21, ki2);  fma2(accI[1][1], qi21,  kr2);
        }
    }

#pragma unroll
    for (int ii = 0; ii < 2; ii++)
#pragma unroll
        for (int j = 0; j < 2; j++) {
            int qg = q0 + lq0 + 2 * ii;
            int p  = p0 + tx + 32 * j;
            float r0v = accR[ii][j].x, i0v = accI[ii][j].x;
            float r1v = accR[ii][j].y, i1v = accI[ii][j].y;
            g_S[h][n][qg][b][p]     = sqrtf(r0v * r0v + i0v * i0v);
            g_S[h][n][qg + 1][b][p] = sqrtf(r1v * r1v + i1v * i1v);
        }
}

// ---------------- kernel 6: softmax over b (sums AC + BD) ----------------
__global__ __launch_bounds__(256) void k_softmax()
{
    int idx = blockIdx.x * 256 + threadIdx.x;
    int p  = idx % P_;
    int q  = (idx / P_) % Q_;
    int hn = idx / (P_ * Q_);
    size_t off = (((size_t)hn * Q_ + q) * B_) * P_ + p;
    float* baseA = &g_S[0][0][0][0][0] + off;
    const float* baseB = &g_S2[0][0][0][0][0] + off;
    float v0 = (baseA[0 * P_] + baseB[0 * P_]) * TEMPF;
    float v1 = (baseA[1 * P_] + baseB[1 * P_]) * TEMPF;
    float v2 = (baseA[2 * P_] + baseB[2 * P_]) * TEMPF;
    float v3 = (baseA[3 * P_] + baseB[3 * P_]) * TEMPF;
    float m = fmaxf(fmaxf(v0, v1), fmaxf(v2, v3));
    v0 = __expf(v0 - m); v1 = __expf(v1 - m); v2 = __expf(v2 - m); v3 = __expf(v3 - m);
    float inv = 1.f / (v0 + v1 + v2 + v3);
    baseA[0 * P_] = v0 * inv;
    baseA[1 * P_] = v1 * inv;
    baseA[2 * P_] = v2 * inv;
    baseA[3 * P_] = v3 * inv;
}

// ---------------- kernel 7: output aggregation (GEMM per (h,n,b,q-tile)) ----------------
// grid (4 q-tiles of 32, B, H*N), block 256: tx(16)->4d, ty(16)->2q
__global__ __launch_bounds__(256) void k_out(
    const float* __restrict__ vr, const float* __restrict__ vi,
    float* __restrict__ out)
{
    int b = blockIdx.y;
    int h = blockIdx.z / N_, n = blockIdx.z % N_;
    int q0 = blockIdx.x * 32;

    __shared__ float aff_s[32][64];          // [q][p-chunk]
    __shared__ float vr_s[64][D_], vi_s[64][D_];

    int t = threadIdx.x;
    int tx = t & 15, ty = t >> 4;
    int d0 = tx * 4, lq0 = ty * 2;

    float2 cr[2][2], ci[2][2];
#pragma unroll
    for (int i = 0; i < 2; i++)
#pragma unroll
        for (int j = 0; j < 2; j++) { cr[i][j] = make_float2(0.f, 0.f); ci[i][j] = make_float2(0.f, 0.f); }

    for (int c = 0; c < 2; c++) {
        __syncthreads();
        int p0 = c * 64;
        for (int i = t; i < 32 * 64; i += 256) {
            int lq = i >> 6, pp = i & 63;
            aff_s[lq][pp] = g_S[h][n][q0 + lq][b][p0 + pp];
        }
        for (int i = t; i < 64 * D_; i += 256) {
            int pp = i >> 6, d = i & 63;
            size_t off = (((size_t)n * P_ + p0 + pp) * B_ + b) * D_ + d;
            vr_s[pp][d] = vr[off];
            vi_s[pp][d] = vi[off];
        }
        __syncthreads();

#pragma unroll 4
        for (int pp = 0; pp < 64; pp++) {
            float2 v_r0 = *(const float2*)&vr_s[pp][d0];
            float2 v_r1 = *(const float2*)&vr_s[pp][d0 + 2];
            float2 v_i0 = *(const float2*)&vi_s[pp][d0];
            float2 v_i1 = *(const float2*)&vi_s[pp][d0 + 2];
#pragma unroll
            for (int i = 0; i < 2; i++) {
                float2 a2 = dup2(aff_s[lq0 + i][pp]);
                fma2(cr[i][0], a2, v_r0);  fma2(cr[i][1], a2, v_r1);
                fma2(ci[i][0], a2, v_i0);  fma2(ci[i][1], a2, v_i1);
            }
        }
    }

#pragma unroll
    for (int i = 0; i < 2; i++) {
        int qg = q0 + lq0 + i;
        size_t o = (((size_t)n * Q_ + qg) * B_ + b) * (H_ * D_) + h * D_ + d0;
        *(float2*)(out + o)     = cr[i][0];
        *(float2*)(out + o + 2) = cr[i][1];
        size_t oi = o + (size_t)N_ * Q_ * B_ * H_ * D_;
        *(float2*)(out + oi)     = ci[i][0];
        *(float2*)(out + oi + 2) = ci[i][1];
    }
}

// ---------------- launch ----------------
extern "C" void kernel_launch(void* const* d_in, const int* in_sizes, int n_in,
                              void* d_out, int out_size)
{
    const float* query_r = (const float*)d_in[0];
    const float* query_i = (const float*)d_in[1];
    const float* key_r   = (const float*)d_in[2];
    const float* key_i   = (const float*)d_in[3];
    const float* val_r   = (const float*)d_in[4];
    const float* val_i   = (const float*)d_in[5];
    const float* emb_r   = (const float*)d_in[6];
    const float* emb_i   = (const float*)d_in[7];
    const float* WKr_w   = (const float*)d_in[8];
    const float* WKr_b   = (const float*)d_in[9];
    const float* WKi_w   = (const float*)d_in[10];
    const float* WKi_b   = (const float*)d_in[11];
    const float* WKRr_w  = (const float*)d_in[12];
    const float* WKRr_b  = (const float*)d_in[13];
    const float* WKRi_w  = (const float*)d_in[14];
    const float* WKRi_b  = (const float*)d_in[15];
    const float* WQr_w   = (const float*)d_in[16];
    const float* WQr_b   = (const float*)d_in[17];
    const float* WQi_w   = (const float*)d_in[18];
    const float* WQi_b   = (const float*)d_in[19];
    const float* ww_r_g  = (const float*)d_in[20];
    const float* ww_r_bt = (const float*)d_in[21];
    const float* ww_i_g  = (const float*)d_in[22];
    const float* ww_i_bt = (const float*)d_in[23];
    const float* wr_r_g  = (const float*)d_in[24];
    const float* wr_r_bt = (const float*)d_in[25];
    const float* wr_i_g  = (const float*)d_in[26];
    const float* wr_i_bt = (const float*)d_in[27];

    cudaFuncSetAttribute(k_bd, cudaFuncAttributeMaxDynamicSharedMemorySize, SMEM_BD);

    k_proj<<<dim3(32, H_, 2), 256>>>(key_r, key_i, query_r, query_i,
                                     WKr_w, WKr_b, WKi_w, WKi_b,
                                     WQr_w, WQr_b, WQi_w, WQi_b);
    k_stats<<<dim3(N_, H_, 4), 512>>>();
    k_tvec<<<dim3(32, H_), 256>>>(WKRr_w, WKRr_b, WKRi_w, WKRi_b,
                                  wr_r_g, wr_r_bt, wr_i_g, wr_i_bt);
    k_bd<<<ROWS_, 256, SMEM_BD>>>((const float4*)emb_r, (const float4*)emb_i);
    k_ac<<<dim3(8, B_, H_ * N_), 256>>>(ww_r_g, ww_r_bt, ww_i_g, ww_i_bt);
    k_softmax<<<1024, 256>>>();
    k_out<<<dim3(4, B_, H_ * N_), 256>>>(val_r, val_i, (float*)d_out);
}